// round 9
// baseline (speedup 1.0000x reference)
#include <cuda_runtime.h>
#include <cstdint>

#define DIM    1024
#define BATCH  2
#define SEQ    2048
#define NHEADS 16
#define DH     64
#define TOKENS (BATCH*SEQ)      // 4096
#define QKV_N  (3*DIM)          // 3072

typedef unsigned long long u64;

// Scratch (allocation-free rule: __device__ globals)
__device__ float g_q[BATCH*NHEADS*SEQ*DH];   // [b,h,n,d]
__device__ float g_k[BATCH*NHEADS*SEQ*DH];
__device__ float g_v[BATCH*NHEADS*SEQ*DH];
__device__ float g_o[TOKENS*DIM];            // [b,n,c]

// ---------------------------------------------------------------------------
// Packed fp32x2 helpers (SASS FFMA2; PTX fma.rn.f32x2, plain sm_100+)
// ---------------------------------------------------------------------------
__device__ __forceinline__ u64 ffma2(u64 a, u64 b, u64 c) {
    u64 d;
    asm("fma.rn.f32x2 %0, %1, %2, %3;" : "=l"(d) : "l"(a), "l"(b), "l"(c));
    return d;
}
__device__ __forceinline__ float2 unpack2(u64 v) {
    float2 r;
    asm("mov.b64 {%0, %1}, %2;" : "=f"(r.x), "=f"(r.y) : "l"(v));
    return r;
}
__device__ __forceinline__ u64 pack2(float x, float y) {
    u64 r;
    asm("mov.b64 %0, {%1, %2};" : "=l"(r) : "f"(x), "f"(y));
    return r;
}

// ---------------------------------------------------------------------------
// GEMM: C[M,Nout] = A[M,K] @ W[Nout,K]^T + bias.  BM=BN=128, BK=16.
// k-PAIR PACKED: smem rows are k2 = k/2; element = f32x2 (A[m][2k2], A[m][2k2+1]).
// acc lanes = k-parity partial sums (summed in epilogue). 8x8 micro-tile:
// per k-pair 8 LDS.128 + 64 FFMA2 (128 MAC) = 1.0 B/MAC. Double-buffered.
// MODE 0: scatter qkv -> g_q/g_k/g_v.  MODE 1: A = g_o, write C directly.
// ---------------------------------------------------------------------------
#define AS_STRIDE 260   // floats per k2-row: 128 f32x2 = 256 + 4 pad (16B-mult)

template<int MODE>
__global__ __launch_bounds__(256, 1)
void gemm2(const float* __restrict__ A, const float* __restrict__ W,
           const float* __restrict__ bias, float* __restrict__ C,
           int K, int Nout)
{
    __shared__ float AsF[2][8*AS_STRIDE];
    __shared__ float BsF[2][8*AS_STRIDE];

    const int tid = threadIdx.x;
    const int tx  = tid & 15;
    const int ty  = tid >> 4;
    const int m0  = blockIdx.y << 7;
    const int n0  = blockIdx.x << 7;
    const int r0  = tid >> 2;        // 0..63
    const int kq  = tid & 3;         // quad within BK=16

    const float* Abase = (MODE == 1) ? (const float*)g_o : A;
    const float* Ag0 = Abase + (size_t)(m0 + r0)      * K + kq*4;
    const float* Ag1 = Abase + (size_t)(m0 + r0 + 64) * K + kq*4;
    const float* Wg0 = W     + (size_t)(n0 + r0)      * K + kq*4;
    const float* Wg1 = W     + (size_t)(n0 + r0 + 64) * K + kq*4;

    u64 acc[8][8] = {};   // f32x2: lanes = (even-k, odd-k) partial sums

    float4 pa0 = *reinterpret_cast<const float4*>(Ag0);
    float4 pa1 = *reinterpret_cast<const float4*>(Ag1);
    float4 pb0 = *reinterpret_cast<const float4*>(Wg0);
    float4 pb1 = *reinterpret_cast<const float4*>(Wg1);

#define G2_STORE(BUF) do {                                                    \
    float* As_ = AsF[BUF]; float* Bs_ = BsF[BUF];                             \
    *reinterpret_cast<float2*>(&As_[(2*kq+0)*AS_STRIDE + r0*2])        = make_float2(pa0.x, pa0.y); \
    *reinterpret_cast<float2*>(&As_[(2*kq+1)*AS_STRIDE + r0*2])        = make_float2(pa0.z, pa0.w); \
    *reinterpret_cast<float2*>(&As_[(2*kq+0)*AS_STRIDE + (r0+64)*2])   = make_float2(pa1.x, pa1.y); \
    *reinterpret_cast<float2*>(&As_[(2*kq+1)*AS_STRIDE + (r0+64)*2])   = make_float2(pa1.z, pa1.w); \
    *reinterpret_cast<float2*>(&Bs_[(2*kq+0)*AS_STRIDE + r0*2])        = make_float2(pb0.x, pb0.y); \
    *reinterpret_cast<float2*>(&Bs_[(2*kq+1)*AS_STRIDE + r0*2])        = make_float2(pb0.z, pb0.w); \
    *reinterpret_cast<float2*>(&Bs_[(2*kq+0)*AS_STRIDE + (r0+64)*2])   = make_float2(pb1.x, pb1.y); \
    *reinterpret_cast<float2*>(&Bs_[(2*kq+1)*AS_STRIDE + (r0+64)*2])   = make_float2(pb1.z, pb1.w); \
} while (0)

    G2_STORE(0);
    __syncthreads();

    const int NSTG = K >> 4;
    for (int s = 0; s < NSTG; ++s) {
        const int cur = s & 1;
        if (s + 1 < NSTG) {   // prefetch next stage gmem -> regs
            pa0 = *reinterpret_cast<const float4*>(Ag0 + (s+1)*16);
            pa1 = *reinterpret_cast<const float4*>(Ag1 + (s+1)*16);
            pb0 = *reinterpret_cast<const float4*>(Wg0 + (s+1)*16);
            pb1 = *reinterpret_cast<const float4*>(Wg1 + (s+1)*16);
        }
#pragma unroll
        for (int k2 = 0; k2 < 8; ++k2) {
            const float* as = AsF[cur] + k2*AS_STRIDE + ty*16;
            const float* bs = BsF[cur] + k2*AS_STRIDE + tx*16;
            u64 a2[8], b2[8];
#pragma unroll
            for (int u = 0; u < 4; ++u) {
                ulonglong2 ua = *reinterpret_cast<const ulonglong2*>(as + u*4);
                a2[2*u] = ua.x; a2[2*u+1] = ua.y;
                ulonglong2 ub = *reinterpret_cast<const ulonglong2*>(bs + u*4);
                b2[2*u] = ub.x; b2[2*u+1] = ub.y;
            }
#pragma unroll
            for (int i = 0; i < 8; ++i)
#pragma unroll
                for (int j = 0; j < 8; ++j)
                    acc[i][j] = ffma2(a2[i], b2[j], acc[i][j]);
        }
        if (s + 1 < NSTG) {
            G2_STORE((s+1) & 1);
            __syncthreads();
        }
    }

#pragma unroll
    for (int i = 0; i < 8; ++i) {
        const int m = m0 + ty*8 + i;
#pragma unroll
        for (int j = 0; j < 8; ++j) {
            const int jg = n0 + tx*8 + j;
            float2 p = unpack2(acc[i][j]);
            const float v = p.x + p.y + bias[jg];
            if (MODE == 0) {
                const int c3  = jg >> 10;
                const int rem = jg & 1023;
                const int h   = rem >> 6;
                const int d   = rem & 63;
                const int b   = m >> 11;
                const int n   = m & 2047;
                const int dst = ((b*NHEADS + h)*SEQ + n)*DH + d;
                float* pdst = (c3 == 0) ? g_q : (c3 == 1) ? g_k : g_v;
                pdst[dst] = v;
            } else {
                C[(size_t)m * Nout + jg] = v;
            }
        }
    }
#undef G2_STORE
}

// ---------------------------------------------------------------------------
// Flash attention: Br=128, Bc=64, 256 threads (16 tx x 16 ty), f32x2 packed.
// S-phase: d-PAIR packed (Qp/Kp stored d-pair-interleaved); s lanes = d-parity
//          partials; micro-tile 8(i) x 4(j).
// PV-phase: j-PAIR packed (V stored d-major so (j,j+1) contiguous; P rows
//          naturally j-contiguous); o lanes = j-parity partials; 8(i) x 4(d).
// ---------------------------------------------------------------------------
#define QP_STRIDE 260   // floats per d2-row of Qp (128 f32x2 + pad)
#define KP_STRIDE 132   // floats per d2-row of Kp ( 64 f32x2 + pad)
#define VT_STRIDE 76    // floats per d-row  of Vt ( 64 + pad, 16B-mult)
#define PS_STRIDE 68    // floats per i-row  of Ps ( 64 + pad, 16B-mult)
#define SM_QP 0
#define SM_KP (32*QP_STRIDE)                 // 8320
#define SM_VT (SM_KP + 32*KP_STRIDE)         // 12544
#define SM_PS (SM_VT + 64*VT_STRIDE)         // 17408
#define ATTN_SMEM ((SM_PS + 128*PS_STRIDE) * 4)   // 104448 bytes

__global__ __launch_bounds__(256, 1)
void attn2()
{
    extern __shared__ float sm[];
    float* Qp = sm + SM_QP;   // [d2=32][i=128] f32x2 (Q[i][2d2],Q[i][2d2+1])*scale
    float* Kp = sm + SM_KP;   // [d2=32][j=64]  f32x2
    float* Vt = sm + SM_VT;   // [d=64][j=64]   floats, d-major
    float* Ps = sm + SM_PS;   // [i=128][j=64]  floats

    const int tid = threadIdx.x;
    const int tx  = tid & 15;
    const int ty  = tid >> 4;
    const int bh  = blockIdx.y;          // b*NHEADS + h
    const int q0  = blockIdx.x << 7;

    const float* Qg = g_q + (size_t)bh * SEQ * DH;
    const float* Kg = g_k + (size_t)bh * SEQ * DH;
    const float* Vg = g_v + (size_t)bh * SEQ * DH;

    // Load Q tile once: pair-interleave + fold scale = 0.125
    {
        const int r    = tid >> 1;        // 0..127
        const int half = (tid & 1) * 32;
#pragma unroll
        for (int v = 0; v < 8; ++v) {
            const int d = half + v*4;
            float4 q4 = *reinterpret_cast<const float4*>(
                Qg + (size_t)(q0 + r)*DH + d);
            *reinterpret_cast<float2*>(&Qp[(d>>1)*QP_STRIDE + r*2]) =
                make_float2(q4.x*0.125f, q4.y*0.125f);
            *reinterpret_cast<float2*>(&Qp[((d>>1)+1)*QP_STRIDE + r*2]) =
                make_float2(q4.z*0.125f, q4.w*0.125f);
        }
    }

    u64 o2[8][4] = {};                   // lanes = j-parity partials
    float mrow[8], lsum[8] = {};
#pragma unroll
    for (int i = 0; i < 8; ++i) mrow[i] = -1e30f;

    const int kr = tid >> 2;             // key row 0..63
    const int kq4 = (tid & 3) * 4;       // interleaved d base

    for (int kt = 0; kt < SEQ; kt += 64) {
        // gmem prefetch K,V -> regs (d = kq4 + 16v)
        float4 kv[4], vv[4];
#pragma unroll
        for (int v = 0; v < 4; ++v) {
            const int d = kq4 + v*16;
            kv[v] = *reinterpret_cast<const float4*>(
                Kg + (size_t)(kt + kr)*DH + d);
            vv[v] = *reinterpret_cast<const float4*>(
                Vg + (size_t)(kt + kr)*DH + d);
        }
        __syncthreads();   // prev PV done (Kp/Vt free); Qp visible on iter 0
#pragma unroll
        for (int v = 0; v < 4; ++v) {
            const int d = kq4 + v*16;
            *reinterpret_cast<float2*>(&Kp[(d>>1)*KP_STRIDE + kr*2]) =
                make_float2(kv[v].x, kv[v].y);
            *reinterpret_cast<float2*>(&Kp[((d>>1)+1)*KP_STRIDE + kr*2]) =
                make_float2(kv[v].z, kv[v].w);
            Vt[(d+0)*VT_STRIDE + kr] = vv[v].x;
            Vt[(d+1)*VT_STRIDE + kr] = vv[v].y;
            Vt[(d+2)*VT_STRIDE + kr] = vv[v].z;
            Vt[(d+3)*VT_STRIDE + kr] = vv[v].w;
        }
        __syncthreads();

        // ---- S = (Q*scale) @ K^T  (d-pair packed, 8x4 per thread) ----
        u64 s2[8][4] = {};
#pragma unroll 4
        for (int d2 = 0; d2 < 32; ++d2) {
            const float* qp = Qp + d2*QP_STRIDE + ty*16;
            const float* kp = Kp + d2*KP_STRIDE + tx*8;
            u64 a2[8], b2[4];
#pragma unroll
            for (int u = 0; u < 4; ++u) {
                ulonglong2 ua = *reinterpret_cast<const ulonglong2*>(qp + u*4);
                a2[2*u] = ua.x; a2[2*u+1] = ua.y;
            }
            {
                ulonglong2 ub0 = *reinterpret_cast<const ulonglong2*>(kp);
                ulonglong2 ub1 = *reinterpret_cast<const ulonglong2*>(kp + 4);
                b2[0] = ub0.x; b2[1] = ub0.y; b2[2] = ub1.x; b2[3] = ub1.y;
            }
#pragma unroll
            for (int i = 0; i < 8; ++i)
#pragma unroll
                for (int j = 0; j < 4; ++j)
                    s2[i][j] = ffma2(a2[i], b2[j], s2[i][j]);
        }
        float s[8][4];
#pragma unroll
        for (int i = 0; i < 8; ++i)
#pragma unroll
            for (int j = 0; j < 4; ++j) {
                float2 t = unpack2(s2[i][j]);
                s[i][j] = t.x + t.y;
            }

        // ---- online softmax (rows reduce across the 16 tx lanes) ----
#pragma unroll
        for (int i = 0; i < 8; ++i) {
            float mx = fmaxf(fmaxf(s[i][0], s[i][1]), fmaxf(s[i][2], s[i][3]));
            mx = fmaxf(mx, __shfl_xor_sync(0xffffffffu, mx, 1));
            mx = fmaxf(mx, __shfl_xor_sync(0xffffffffu, mx, 2));
            mx = fmaxf(mx, __shfl_xor_sync(0xffffffffu, mx, 4));
            mx = fmaxf(mx, __shfl_xor_sync(0xffffffffu, mx, 8));
            const float mnew = fmaxf(mrow[i], mx);
            const float corr = __expf(mrow[i] - mnew);
            mrow[i] = mnew;
            float ps = 0.f;
#pragma unroll
            for (int j = 0; j < 4; ++j) {
                const float p = __expf(s[i][j] - mnew);
                s[i][j] = p;
                ps += p;
            }
            ps += __shfl_xor_sync(0xffffffffu, ps, 1);
            ps += __shfl_xor_sync(0xffffffffu, ps, 2);
            ps += __shfl_xor_sync(0xffffffffu, ps, 4);
            ps += __shfl_xor_sync(0xffffffffu, ps, 8);
            lsum[i] = lsum[i]*corr + ps;
            const u64 c2 = pack2(corr, corr);
#pragma unroll
            for (int d = 0; d < 4; ++d)
                o2[i][d] = ffma2(o2[i][d], c2, 0ULL);   // o *= corr (both lanes)
        }

        // ---- store P (natural layout) ----
#pragma unroll
        for (int i = 0; i < 8; ++i)
            *reinterpret_cast<float4*>(&Ps[(ty*8+i)*PS_STRIDE + tx*4]) =
                make_float4(s[i][0], s[i][1], s[i][2], s[i][3]);
        __syncthreads();

        // ---- O += P @ V  (j-pair packed, 8x4 per thread) ----
#pragma unroll 2
        for (int j0 = 0; j0 < 64; j0 += 4) {
            u64 v2[4][2];
#pragma unroll
            for (int dd = 0; dd < 4; ++dd) {
                ulonglong2 uv = *reinterpret_cast<const ulonglong2*>(
                    &Vt[(tx*4+dd)*VT_STRIDE + j0]);
                v2[dd][0] = uv.x; v2[dd][1] = uv.y;
            }
#pragma unroll
            for (int ii = 0; ii < 8; ++ii) {
                ulonglong2 up = *reinterpret_cast<const ulonglong2*>(
                    &Ps[(ty*8+ii)*PS_STRIDE + j0]);
#pragma unroll
                for (int dd = 0; dd < 4; ++dd)
                    o2[ii][dd] = ffma2(up.x, v2[dd][0], o2[ii][dd]);
#pragma unroll
                for (int dd = 0; dd < 4; ++dd)
                    o2[ii][dd] = ffma2(up.y, v2[dd][1], o2[ii][dd]);
            }
        }
    }

    // normalize + write g_o [b, n, h*64 + d]
    const int b = bh >> 4;
    const int h = bh & 15;
#pragma unroll
    for (int i = 0; i < 8; ++i) {
        const float inv = 1.0f / lsum[i];
        const int n = q0 + ty*8 + i;
        float ov[4];
#pragma unroll
        for (int dd = 0; dd < 4; ++dd) {
            float2 t = unpack2(o2[i][dd]);
            ov[dd] = (t.x + t.y) * inv;
        }
        *reinterpret_cast<float4*>(
            &g_o[((size_t)(b*SEQ + n))*DIM + h*DH + tx*4]) =
            make_float4(ov[0], ov[1], ov[2], ov[3]);
    }
}

// ---------------------------------------------------------------------------
// Launch: 3 kernels on the default stream (graph-capturable, allocation-free)
// ---------------------------------------------------------------------------
extern "C" void kernel_launch(void* const* d_in, const int* in_sizes, int n_in,
                              void* d_out, int out_size)
{
    const float* x      = (const float*)d_in[0];   // [2,2048,1024]
    const float* qkv_w  = (const float*)d_in[1];   // [3072,1024]
    const float* qkv_b  = (const float*)d_in[2];   // [3072]
    const float* proj_w = (const float*)d_in[3];   // [1024,1024]
    const float* proj_b = (const float*)d_in[4];   // [1024]
    float* out = (float*)d_out;                    // [2,2048,1024]

    cudaFuncSetAttribute(attn2, cudaFuncAttributeMaxDynamicSharedMemorySize,
                         ATTN_SMEM);

    dim3 blk(256);

    // 1) QKV projection + bias + scatter into [b,h,n,d] Q/K/V
    gemm2<0><<<dim3(QKV_N/128, TOKENS/128), blk>>>(
        x, qkv_w, qkv_b, nullptr, DIM, QKV_N);

    // 2) Attention (flash, online softmax, f32x2) -> g_o [b,n,c]
    attn2<<<dim3(SEQ/128, BATCH*NHEADS), blk, ATTN_SMEM>>>();

    // 3) Output projection + bias -> d_out
    gemm2<1><<<dim3(DIM/128, TOKENS/128), blk>>>(
        nullptr, proj_w, proj_b, out, DIM, DIM);
}

// round 10
// speedup vs baseline: 2.0542x; 2.0542x over previous
#include <cuda_runtime.h>
#include <cuda_bf16.h>
#include <cstdint>

#define DIM    1024
#define BATCH  2
#define SEQ    2048
#define NHEADS 16
#define DH     64
#define TOKENS (BATCH*SEQ)      // 4096
#define QKV_N  (3*DIM)          // 3072
#define KP     3072             // split K' = 3*1024

// ---------------- scratch (__device__ globals; allocation-free rule) --------
__device__ float g_q[BATCH*NHEADS*SEQ*DH];   // [b,h,n,d]
__device__ float g_k[BATCH*NHEADS*SEQ*DH];
__device__ float g_v[BATCH*NHEADS*SEQ*DH];
__device__ float g_o[TOKENS*DIM];            // [b,n,c]

__device__ __align__(16) __nv_bfloat16 g_xs   [TOKENS*KP]; // x split   [hi|lo|hi]
__device__ __align__(16) __nv_bfloat16 g_os   [TOKENS*KP]; // g_o split [hi|lo|hi]
__device__ __align__(16) __nv_bfloat16 g_qkvw [QKV_N*KP];  // qkv_w     [hi|hi|lo]
__device__ __align__(16) __nv_bfloat16 g_projw[DIM*KP];    // proj_w    [hi|hi|lo]

// ---------------------------------------------------------------------------
// PTX helpers (all plain sm_80-era PTX; valid on compute_103)
// ---------------------------------------------------------------------------
__device__ __forceinline__ uint32_t smem_u32(const void* p) {
    uint32_t a;
    asm("{ .reg .u64 t; cvta.to.shared.u64 t, %1; cvt.u32.u64 %0, t; }"
        : "=r"(a) : "l"(p));
    return a;
}
__device__ __forceinline__ void cp16(uint32_t dst, const void* src) {
    asm volatile("cp.async.cg.shared.global [%0], [%1], 16;"
                 :: "r"(dst), "l"(src) : "memory");
}
#define CP_COMMIT() asm volatile("cp.async.commit_group;" ::: "memory")
#define CP_WAIT1()  asm volatile("cp.async.wait_group 1;"  ::: "memory")

__device__ __forceinline__ void ldsm4(uint32_t* r, uint32_t a) {
    asm volatile("ldmatrix.sync.aligned.m8n8.x4.shared.b16 {%0,%1,%2,%3}, [%4];"
                 : "=r"(r[0]), "=r"(r[1]), "=r"(r[2]), "=r"(r[3]) : "r"(a));
}
__device__ __forceinline__ void mma16816(float* c, const uint32_t* a,
                                         uint32_t b0, uint32_t b1) {
    asm volatile(
        "mma.sync.aligned.m16n8k16.row.col.f32.bf16.bf16.f32 "
        "{%0,%1,%2,%3}, {%4,%5,%6,%7}, {%8,%9}, {%0,%1,%2,%3};"
        : "+f"(c[0]), "+f"(c[1]), "+f"(c[2]), "+f"(c[3])
        : "r"(a[0]), "r"(a[1]), "r"(a[2]), "r"(a[3]), "r"(b0), "r"(b1));
}

// ---------------------------------------------------------------------------
// split_k1024: fp32 [rows,1024] -> bf16 [rows,3072].
// bpat=0 (A side): [hi | lo | hi] ; bpat=1 (B side): [hi | hi | lo]
// ---------------------------------------------------------------------------
__global__ __launch_bounds__(256)
void split_k1024(const float* __restrict__ src, __nv_bfloat16* __restrict__ dst,
                 int bpat)
{
    const int r = blockIdx.x;
    const int k = threadIdx.x << 2;
    float4 v = *reinterpret_cast<const float4*>(src + (size_t)r*1024 + k);
    float f[4] = {v.x, v.y, v.z, v.w};
    __nv_bfloat16 hi[4], lo[4];
#pragma unroll
    for (int i = 0; i < 4; ++i) {
        hi[i] = __float2bfloat16(f[i]);
        lo[i] = __float2bfloat16(f[i] - __bfloat162float(hi[i]));
    }
    __nv_bfloat16* d0 = dst + (size_t)r*KP + k;
    __nv_bfloat162 h01, h23, l01, l23;
    h01.x = hi[0]; h01.y = hi[1]; h23.x = hi[2]; h23.y = hi[3];
    l01.x = lo[0]; l01.y = lo[1]; l23.x = lo[2]; l23.y = lo[3];
    reinterpret_cast<__nv_bfloat162*>(d0)[0] = h01;
    reinterpret_cast<__nv_bfloat162*>(d0)[1] = h23;
    __nv_bfloat16* d1 = d0 + 1024;
    __nv_bfloat16* d2 = d0 + 2048;
    if (bpat) {
        reinterpret_cast<__nv_bfloat162*>(d1)[0] = h01;
        reinterpret_cast<__nv_bfloat162*>(d1)[1] = h23;
        reinterpret_cast<__nv_bfloat162*>(d2)[0] = l01;
        reinterpret_cast<__nv_bfloat162*>(d2)[1] = l23;
    } else {
        reinterpret_cast<__nv_bfloat162*>(d1)[0] = l01;
        reinterpret_cast<__nv_bfloat162*>(d1)[1] = l23;
        reinterpret_cast<__nv_bfloat162*>(d2)[0] = h01;
        reinterpret_cast<__nv_bfloat162*>(d2)[1] = h23;
    }
}

// ---------------------------------------------------------------------------
// mma.sync GEMM: C[M,Nout] = A'[M,K'] @ W'[Nout,K']^T + bias (fp32 accum).
// BM=BN=128, BK=32 bf16, 8 warps (2m x 4n), each warp 64x32 via 4x4 m16n8k16.
// cp.async 3-stage pipeline; smem rows 80B stride -> conflict-free ldmatrix.
// MODE 0: scatter into g_q/g_k/g_v.  MODE 1: write outp[m*DIM + j].
// ---------------------------------------------------------------------------
#define BK         32
#define A_STRIDE_B 80                    // bytes per smem row (32 bf16 + pad)
#define STAGE_OPER (128*A_STRIDE_B)      // 10240 B per operand
#define STAGE_B    (2*STAGE_OPER)        // 20480 B per stage
#define NBUF       3
#define GSMEM      (NBUF*STAGE_B)        // 61440 B
#define NSTG       (KP/BK)               // 96

__device__ __forceinline__ void store_qkv2(int m, int jg, float x, float y) {
    const int c3 = jg >> 10, rem = jg & 1023;
    const int h  = rem >> 6, d = rem & 63;
    const int b  = m >> 11,  n = m & 2047;
    float* p = (c3 == 0) ? g_q : (c3 == 1) ? g_k : g_v;
    *reinterpret_cast<float2*>(&p[((size_t)(b*NHEADS + h)*SEQ + n)*DH + d]) =
        make_float2(x, y);
}

template<int MODE>
__global__ __launch_bounds__(256, 2)
void gemm_mma(const __nv_bfloat16* __restrict__ Ag,
              const __nv_bfloat16* __restrict__ Wg,
              const float* __restrict__ bias, float* __restrict__ outp)
{
    extern __shared__ char smem[];
    const uint32_t sbase = smem_u32(smem);
    const int tid  = threadIdx.x;
    const int lane = tid & 31, wid = tid >> 5;
    const int warp_m = wid >> 2, warp_n = wid & 3;
    const int m0 = blockIdx.y << 7, n0 = blockIdx.x << 7;

    // gmem->smem mapping: 4 cp.async/thread/stage (A rows r,r+64; B rows r,r+64)
    const int rr = tid >> 2;           // 0..63
    const int kc = tid & 3;            // 16B chunk (8 bf16) within BK=32

    const __nv_bfloat16* Ab = Ag + (size_t)m0*KP + kc*8;
    const __nv_bfloat16* Wb = Wg + (size_t)n0*KP + kc*8;

#define LOAD_STAGE(S, BUF) do {                                               \
    const uint32_t sa = sbase + (BUF)*STAGE_B;                                \
    const uint32_t sw = sa + STAGE_OPER;                                      \
    const size_t ko = (size_t)(S)*BK;                                         \
    cp16(sa + rr*A_STRIDE_B + kc*16,        Ab + (size_t)rr*KP + ko);         \
    cp16(sa + (rr+64)*A_STRIDE_B + kc*16,   Ab + (size_t)(rr+64)*KP + ko);    \
    cp16(sw + rr*A_STRIDE_B + kc*16,        Wb + (size_t)rr*KP + ko);         \
    cp16(sw + (rr+64)*A_STRIDE_B + kc*16,   Wb + (size_t)(rr+64)*KP + ko);    \
} while (0)

    // ldmatrix per-lane base offsets (bytes)
    const uint32_t a_off = (uint32_t)((warp_m*64 + (lane & 15))*A_STRIDE_B
                                      + (lane >> 4)*16);
    const uint32_t b_off = (uint32_t)((warp_n*32 + (lane & 7)
                                      + ((lane >> 4) & 1)*8)*A_STRIDE_B
                                      + ((lane >> 3) & 1)*16);

    float acc[4][4][4] = {};

    LOAD_STAGE(0, 0); CP_COMMIT();
    LOAD_STAGE(1, 1); CP_COMMIT();

    for (int s = 0; s < NSTG; ++s) {
        CP_WAIT1();
        __syncthreads();
        if (s + 2 < NSTG) LOAD_STAGE(s + 2, (s + 2) % 3);
        CP_COMMIT();

        const uint32_t ab = sbase + (s % 3)*STAGE_B;
        const uint32_t bb = ab + STAGE_OPER;
#pragma unroll
        for (int kk = 0; kk < 2; ++kk) {
            uint32_t af[4][4], bf[2][4];
#pragma unroll
            for (int mt = 0; mt < 4; ++mt)
                ldsm4(af[mt], ab + a_off + mt*16*A_STRIDE_B + kk*32);
#pragma unroll
            for (int pr = 0; pr < 2; ++pr)
                ldsm4(bf[pr], bb + b_off + pr*16*A_STRIDE_B + kk*32);
#pragma unroll
            for (int mt = 0; mt < 4; ++mt)
#pragma unroll
                for (int nt = 0; nt < 4; ++nt)
                    mma16816(acc[mt][nt], af[mt],
                             bf[nt >> 1][(nt & 1)*2],
                             bf[nt >> 1][(nt & 1)*2 + 1]);
        }
    }
#undef LOAD_STAGE

    // epilogue: frag (c0,c1)=row gr, (c2,c3)=row gr+8; cols tg*2, tg*2+1
    const int gr = lane >> 2, tg = lane & 3;
#pragma unroll
    for (int mt = 0; mt < 4; ++mt) {
        const int r0 = m0 + warp_m*64 + mt*16 + gr;
#pragma unroll
        for (int nt = 0; nt < 4; ++nt) {
            const int col = n0 + warp_n*32 + nt*8 + tg*2;
            const float2 bv = *reinterpret_cast<const float2*>(bias + col);
            const float v00 = acc[mt][nt][0] + bv.x;
            const float v01 = acc[mt][nt][1] + bv.y;
            const float v10 = acc[mt][nt][2] + bv.x;
            const float v11 = acc[mt][nt][3] + bv.y;
            if (MODE == 0) {
                store_qkv2(r0,     col, v00, v01);
                store_qkv2(r0 + 8, col, v10, v11);
            } else {
                *reinterpret_cast<float2*>(&outp[(size_t)r0*DIM + col]) =
                    make_float2(v00, v01);
                *reinterpret_cast<float2*>(&outp[(size_t)(r0+8)*DIM + col]) =
                    make_float2(v10, v11);
            }
        }
    }
}

// ---------------------------------------------------------------------------
// Flash attention (R6, SIMT, proven): Br=128, Bc=64, 256 threads, 8x4 tile.
// ---------------------------------------------------------------------------
#define QT_STRIDE 132
#define ATTN_SMEM ((64*QT_STRIDE + 64*64 + 64*64 + 128*64) * 4)

__global__ __launch_bounds__(256)
void attn128()
{
    extern __shared__ float sm[];
    float* Qt = sm;                        // [64][132]  d-major, scale folded
    float* Kt = sm + 64*QT_STRIDE;         // [64][64]   d-major
    float* Vs = Kt + 64*64;                // [64][64]   natural [j][d]
    float* Ps = Vs + 64*64;                // [128][64]  natural [i][j]

    const int tid = threadIdx.x;
    const int tx  = tid & 15;
    const int ty  = tid >> 4;
    const int bh  = blockIdx.y;
    const int q0  = blockIdx.x << 7;

    const float* Qg = g_q + (size_t)bh * SEQ * DH;
    const float* Kg = g_k + (size_t)bh * SEQ * DH;
    const float* Vg = g_v + (size_t)bh * SEQ * DH;

    {
        const int r  = tid >> 1;
        const int c0 = (tid & 1) * 32;
#pragma unroll
        for (int v = 0; v < 8; ++v) {
            const int d = c0 + v*4;
            float4 q4 = *reinterpret_cast<const float4*>(
                Qg + (size_t)(q0 + r)*DH + d);
            Qt[(d+0)*QT_STRIDE + r] = q4.x * 0.125f;
            Qt[(d+1)*QT_STRIDE + r] = q4.y * 0.125f;
            Qt[(d+2)*QT_STRIDE + r] = q4.z * 0.125f;
            Qt[(d+3)*QT_STRIDE + r] = q4.w * 0.125f;
        }
    }

    float o[8][4]  = {};
    float mrow[8], lsum[8] = {};
#pragma unroll
    for (int i = 0; i < 8; ++i) mrow[i] = -1e30f;

    const int kr = tid >> 2;
    const int kc = (tid & 3) * 16;

    for (int kt = 0; kt < SEQ; kt += 64) {
        float4 kv[4], vv[4];
#pragma unroll
        for (int v = 0; v < 4; ++v) {
            kv[v] = *reinterpret_cast<const float4*>(
                Kg + (size_t)(kt + kr)*DH + kc + v*4);
            vv[v] = *reinterpret_cast<const float4*>(
                Vg + (size_t)(kt + kr)*DH + kc + v*4);
        }
        __syncthreads();
#pragma unroll
        for (int v = 0; v < 4; ++v) {
            const int d = kc + v*4;
            Kt[(d+0)*64 + kr] = kv[v].x;
            Kt[(d+1)*64 + kr] = kv[v].y;
            Kt[(d+2)*64 + kr] = kv[v].z;
            Kt[(d+3)*64 + kr] = kv[v].w;
            *reinterpret_cast<float4*>(&Vs[kr*64 + d]) = vv[v];
        }
        __syncthreads();

        float s[8][4] = {};
#pragma unroll 8
        for (int d = 0; d < 64; ++d) {
            float4 x0 = *reinterpret_cast<const float4*>(&Qt[d*QT_STRIDE + ty*8]);
            float4 x1 = *reinterpret_cast<const float4*>(&Qt[d*QT_STRIDE + ty*8 + 4]);
            float4 y  = *reinterpret_cast<const float4*>(&Kt[d*64 + tx*4]);
            float ar[8] = {x0.x,x0.y,x0.z,x0.w, x1.x,x1.y,x1.z,x1.w};
            float br[4] = {y.x, y.y, y.z, y.w};
#pragma unroll
            for (int i = 0; i < 8; ++i)
#pragma unroll
                for (int j = 0; j < 4; ++j)
                    s[i][j] = fmaf(ar[i], br[j], s[i][j]);
        }

#pragma unroll
        for (int i = 0; i < 8; ++i) {
            float mx = fmaxf(fmaxf(s[i][0], s[i][1]), fmaxf(s[i][2], s[i][3]));
            mx = fmaxf(mx, __shfl_xor_sync(0xffffffffu, mx, 1));
            mx = fmaxf(mx, __shfl_xor_sync(0xffffffffu, mx, 2));
            mx = fmaxf(mx, __shfl_xor_sync(0xffffffffu, mx, 4));
            mx = fmaxf(mx, __shfl_xor_sync(0xffffffffu, mx, 8));
            const float mnew = fmaxf(mrow[i], mx);
            const float corr = __expf(mrow[i] - mnew);
            mrow[i] = mnew;
            float ps = 0.f;
#pragma unroll
            for (int j = 0; j < 4; ++j) {
                const float p = __expf(s[i][j] - mnew);
                s[i][j] = p;
                ps += p;
            }
            ps += __shfl_xor_sync(0xffffffffu, ps, 1);
            ps += __shfl_xor_sync(0xffffffffu, ps, 2);
            ps += __shfl_xor_sync(0xffffffffu, ps, 4);
            ps += __shfl_xor_sync(0xffffffffu, ps, 8);
            lsum[i] = lsum[i]*corr + ps;
#pragma unroll
            for (int j = 0; j < 4; ++j) o[i][j] *= corr;
        }

#pragma unroll
        for (int i = 0; i < 8; ++i)
            *reinterpret_cast<float4*>(&Ps[(ty*8+i)*64 + tx*4]) =
                make_float4(s[i][0], s[i][1], s[i][2], s[i][3]);
        __syncthreads();

#pragma unroll 2
        for (int j0 = 0; j0 < 64; j0 += 4) {
            float vr[4][4];
#pragma unroll
            for (int jj = 0; jj < 4; ++jj) {
                float4 v4 = *reinterpret_cast<const float4*>(
                    &Vs[(j0+jj)*64 + tx*4]);
                vr[jj][0] = v4.x; vr[jj][1] = v4.y;
                vr[jj][2] = v4.z; vr[jj][3] = v4.w;
            }
#pragma unroll
            for (int i = 0; i < 8; ++i) {
                float4 p4 = *reinterpret_cast<const float4*>(
                    &Ps[(ty*8+i)*64 + j0]);
                float pv[4] = {p4.x, p4.y, p4.z, p4.w};
#pragma unroll
                for (int jj = 0; jj < 4; ++jj)
#pragma unroll
                    for (int dd = 0; dd < 4; ++dd)
                        o[i][dd] = fmaf(pv[jj], vr[jj][dd], o[i][dd]);
            }
        }
    }

    const int b = bh >> 4;
    const int h = bh & 15;
#pragma unroll
    for (int i = 0; i < 8; ++i) {
        const float inv = 1.0f / lsum[i];
        const int n = q0 + ty*8 + i;
        float4 ov = make_float4(o[i][0]*inv, o[i][1]*inv,
                                o[i][2]*inv, o[i][3]*inv);
        *reinterpret_cast<float4*>(
            &g_o[((size_t)(b*SEQ + n))*DIM + h*DH + tx*4]) = ov;
    }
}

// ---------------------------------------------------------------------------
extern "C" void kernel_launch(void* const* d_in, const int* in_sizes, int n_in,
                              void* d_out, int out_size)
{
    const float* x      = (const float*)d_in[0];
    const float* qkv_w  = (const float*)d_in[1];
    const float* qkv_b  = (const float*)d_in[2];
    const float* proj_w = (const float*)d_in[3];
    const float* proj_b = (const float*)d_in[4];
    float* out = (float*)d_out;

    cudaFuncSetAttribute(attn128, cudaFuncAttributeMaxDynamicSharedMemorySize,
                         ATTN_SMEM);
    cudaFuncSetAttribute(gemm_mma<0>,
                         cudaFuncAttributeMaxDynamicSharedMemorySize, GSMEM);
    cudaFuncSetAttribute(gemm_mma<1>,
                         cudaFuncAttributeMaxDynamicSharedMemorySize, GSMEM);

    float* go_ptr = nullptr;
    cudaGetSymbolAddress((void**)&go_ptr, g_o);
    __nv_bfloat16 *xs_p, *os_p, *qw_p, *pw_p;
    cudaGetSymbolAddress((void**)&xs_p, g_xs);
    cudaGetSymbolAddress((void**)&os_p, g_os);
    cudaGetSymbolAddress((void**)&qw_p, g_qkvw);
    cudaGetSymbolAddress((void**)&pw_p, g_projw);

    dim3 blk(256);

    // 1) bf16 hi/lo splits (K-concat trick)
    split_k1024<<<TOKENS, blk>>>(x,      xs_p, 0);
    split_k1024<<<QKV_N,  blk>>>(qkv_w,  qw_p, 1);
    split_k1024<<<DIM,    blk>>>(proj_w, pw_p, 1);

    // 2) QKV projection (mma.sync bf16 split) + bias + scatter
    gemm_mma<0><<<dim3(QKV_N/128, TOKENS/128), blk, GSMEM>>>(
        xs_p, qw_p, qkv_b, nullptr);

    // 3) Attention (SIMT flash) -> g_o
    attn128<<<dim3(SEQ/128, BATCH*NHEADS), blk, ATTN_SMEM>>>();

    // 4) split g_o, output projection (mma.sync) -> d_out
    split_k1024<<<TOKENS, blk>>>(go_ptr, os_p, 0);
    gemm_mma<1><<<dim3(DIM/128, TOKENS/128), blk, GSMEM>>>(
        os_p, pw_p, proj_b, out);
}

// round 11
// speedup vs baseline: 5.0884x; 2.4770x over previous
#include <cuda_runtime.h>
#include <cuda_bf16.h>
#include <cuda_fp16.h>
#include <cstdint>

#define DIM    1024
#define BATCH  2
#define SEQ    2048
#define NHEADS 16
#define DH     64
#define TOKENS (BATCH*SEQ)      // 4096
#define QKV_N  (3*DIM)          // 3072
#define KP     3072             // split K' = 3*1024

// ---------------- scratch (__device__ globals; allocation-free rule) --------
__device__ __align__(16) __half g_qh[BATCH*NHEADS*SEQ*DH]; // fp16 q (pre-scaled 0.125)
__device__ __align__(16) __half g_kh[BATCH*NHEADS*SEQ*DH]; // fp16 k
__device__ __align__(16) __half g_vh[BATCH*NHEADS*SEQ*DH]; // fp16 v

__device__ __align__(16) __nv_bfloat16 g_xs   [TOKENS*KP]; // x split   [hi|lo|hi]
__device__ __align__(16) __nv_bfloat16 g_os   [TOKENS*KP]; // attn out  [hi|lo|hi]
__device__ __align__(16) __nv_bfloat16 g_qkvw [QKV_N*KP];  // qkv_w     [hi|hi|lo]
__device__ __align__(16) __nv_bfloat16 g_projw[DIM*KP];    // proj_w    [hi|hi|lo]

// ---------------------------------------------------------------------------
// PTX helpers (all plain sm_80-era PTX; valid on compute_103)
// ---------------------------------------------------------------------------
__device__ __forceinline__ uint32_t smem_u32(const void* p) {
    uint32_t a;
    asm("{ .reg .u64 t; cvta.to.shared.u64 t, %1; cvt.u32.u64 %0, t; }"
        : "=r"(a) : "l"(p));
    return a;
}
__device__ __forceinline__ void cp16(uint32_t dst, const void* src) {
    asm volatile("cp.async.cg.shared.global [%0], [%1], 16;"
                 :: "r"(dst), "l"(src) : "memory");
}
#define CP_COMMIT() asm volatile("cp.async.commit_group;" ::: "memory")
#define CP_WAIT0()  asm volatile("cp.async.wait_group 0;"  ::: "memory")
#define CP_WAIT1()  asm volatile("cp.async.wait_group 1;"  ::: "memory")

__device__ __forceinline__ void ldsm4(uint32_t* r, uint32_t a) {
    asm volatile("ldmatrix.sync.aligned.m8n8.x4.shared.b16 {%0,%1,%2,%3}, [%4];"
                 : "=r"(r[0]), "=r"(r[1]), "=r"(r[2]), "=r"(r[3]) : "r"(a));
}
__device__ __forceinline__ void ldsm4t(uint32_t* r, uint32_t a) {
    asm volatile("ldmatrix.sync.aligned.m8n8.x4.trans.shared.b16 {%0,%1,%2,%3}, [%4];"
                 : "=r"(r[0]), "=r"(r[1]), "=r"(r[2]), "=r"(r[3]) : "r"(a));
}
__device__ __forceinline__ void mma_bf(float* c, const uint32_t* a,
                                       uint32_t b0, uint32_t b1) {
    asm volatile(
        "mma.sync.aligned.m16n8k16.row.col.f32.bf16.bf16.f32 "
        "{%0,%1,%2,%3}, {%4,%5,%6,%7}, {%8,%9}, {%0,%1,%2,%3};"
        : "+f"(c[0]), "+f"(c[1]), "+f"(c[2]), "+f"(c[3])
        : "r"(a[0]), "r"(a[1]), "r"(a[2]), "r"(a[3]), "r"(b0), "r"(b1));
}
__device__ __forceinline__ void mma_h(float* c, uint32_t a0, uint32_t a1,
                                      uint32_t a2, uint32_t a3,
                                      uint32_t b0, uint32_t b1) {
    asm volatile(
        "mma.sync.aligned.m16n8k16.row.col.f32.f16.f16.f32 "
        "{%0,%1,%2,%3}, {%4,%5,%6,%7}, {%8,%9}, {%0,%1,%2,%3};"
        : "+f"(c[0]), "+f"(c[1]), "+f"(c[2]), "+f"(c[3])
        : "r"(a0), "r"(a1), "r"(a2), "r"(a3), "r"(b0), "r"(b1));
}

// ---------------------------------------------------------------------------
// split_k1024: fp32 [rows,1024] -> bf16 [rows,3072].
// bpat=0 (A side): [hi | lo | hi] ; bpat=1 (B side): [hi | hi | lo]
// ---------------------------------------------------------------------------
__global__ __launch_bounds__(256)
void split_k1024(const float* __restrict__ src, __nv_bfloat16* __restrict__ dst,
                 int bpat)
{
    const int r = blockIdx.x;
    const int k = threadIdx.x << 2;
    float4 v = *reinterpret_cast<const float4*>(src + (size_t)r*1024 + k);
    float f[4] = {v.x, v.y, v.z, v.w};
    __nv_bfloat16 hi[4], lo[4];
#pragma unroll
    for (int i = 0; i < 4; ++i) {
        hi[i] = __float2bfloat16(f[i]);
        lo[i] = __float2bfloat16(f[i] - __bfloat162float(hi[i]));
    }
    __nv_bfloat16* d0 = dst + (size_t)r*KP + k;
    __nv_bfloat162 h01, h23, l01, l23;
    h01.x = hi[0]; h01.y = hi[1]; h23.x = hi[2]; h23.y = hi[3];
    l01.x = lo[0]; l01.y = lo[1]; l23.x = lo[2]; l23.y = lo[3];
    reinterpret_cast<__nv_bfloat162*>(d0)[0] = h01;
    reinterpret_cast<__nv_bfloat162*>(d0)[1] = h23;
    __nv_bfloat16* d1 = d0 + 1024;
    __nv_bfloat16* d2 = d0 + 2048;
    if (bpat) {
        reinterpret_cast<__nv_bfloat162*>(d1)[0] = h01;
        reinterpret_cast<__nv_bfloat162*>(d1)[1] = h23;
        reinterpret_cast<__nv_bfloat162*>(d2)[0] = l01;
        reinterpret_cast<__nv_bfloat162*>(d2)[1] = l23;
    } else {
        reinterpret_cast<__nv_bfloat162*>(d1)[0] = l01;
        reinterpret_cast<__nv_bfloat162*>(d1)[1] = l23;
        reinterpret_cast<__nv_bfloat162*>(d2)[0] = h01;
        reinterpret_cast<__nv_bfloat162*>(d2)[1] = h23;
    }
}

// ---------------------------------------------------------------------------
// mma.sync GEMM (R9, proven): C = A'[M,K'] @ W'[Nout,K']^T + bias (fp32 acc).
// BM=BN=128, BK=32 bf16, 8 warps (2m x 4n). 3-stage cp.async pipeline.
// MODE 0: write q/k/v as fp16 to g_qh/g_kh/g_vh (q pre-scaled by 0.125).
// MODE 1: write fp32 outp[m*DIM + j].
// ---------------------------------------------------------------------------
#define BK         32
#define A_STRIDE_B 80
#define STAGE_OPER (128*A_STRIDE_B)
#define STAGE_B    (2*STAGE_OPER)
#define GSMEM      (3*STAGE_B)
#define NSTG       (KP/BK)

__device__ __forceinline__ void store_qkv_h(int m, int col, float x, float y) {
    const int c3 = col >> 10;
    const int h  = (col >> 6) & 15, d = col & 63;
    const int b  = m >> 11,  n = m & 2047;
    const float sc = (c3 == 0) ? 0.125f : 1.0f;
    __half* p = (c3 == 0) ? g_qh : (c3 == 1) ? g_kh : g_vh;
    *reinterpret_cast<__half2*>(
        &p[((size_t)((b << 4) + h)*SEQ + n)*DH + d]) =
        __floats2half2_rn(x*sc, y*sc);
}

template<int MODE>
__global__ __launch_bounds__(256, 2)
void gemm_mma(const __nv_bfloat16* __restrict__ Ag,
              const __nv_bfloat16* __restrict__ Wg,
              const float* __restrict__ bias, float* __restrict__ outp)
{
    extern __shared__ char smem[];
    const uint32_t sbase = smem_u32(smem);
    const int tid  = threadIdx.x;
    const int lane = tid & 31, wid = tid >> 5;
    const int warp_m = wid >> 2, warp_n = wid & 3;
    const int m0 = blockIdx.y << 7, n0 = blockIdx.x << 7;

    const int rr = tid >> 2;
    const int kc = tid & 3;

    const __nv_bfloat16* Ab = Ag + (size_t)m0*KP + kc*8;
    const __nv_bfloat16* Wb = Wg + (size_t)n0*KP + kc*8;

#define LOAD_STAGE(S, BUF) do {                                               \
    const uint32_t sa = sbase + (BUF)*STAGE_B;                                \
    const uint32_t sw = sa + STAGE_OPER;                                      \
    const size_t ko = (size_t)(S)*BK;                                         \
    cp16(sa + rr*A_STRIDE_B + kc*16,        Ab + (size_t)rr*KP + ko);         \
    cp16(sa + (rr+64)*A_STRIDE_B + kc*16,   Ab + (size_t)(rr+64)*KP + ko);    \
    cp16(sw + rr*A_STRIDE_B + kc*16,        Wb + (size_t)rr*KP + ko);         \
    cp16(sw + (rr+64)*A_STRIDE_B + kc*16,   Wb + (size_t)(rr+64)*KP + ko);    \
} while (0)

    const uint32_t a_off = (uint32_t)((warp_m*64 + (lane & 15))*A_STRIDE_B
                                      + (lane >> 4)*16);
    const uint32_t b_off = (uint32_t)((warp_n*32 + (lane & 7)
                                      + ((lane >> 4) & 1)*8)*A_STRIDE_B
                                      + ((lane >> 3) & 1)*16);

    float acc[4][4][4] = {};

    LOAD_STAGE(0, 0); CP_COMMIT();
    LOAD_STAGE(1, 1); CP_COMMIT();

    for (int s = 0; s < NSTG; ++s) {
        CP_WAIT1();
        __syncthreads();
        if (s + 2 < NSTG) LOAD_STAGE(s + 2, (s + 2) % 3);
        CP_COMMIT();

        const uint32_t ab = sbase + (s % 3)*STAGE_B;
        const uint32_t bb = ab + STAGE_OPER;
#pragma unroll
        for (int kk = 0; kk < 2; ++kk) {
            uint32_t af[4][4], bf[2][4];
#pragma unroll
            for (int mt = 0; mt < 4; ++mt)
                ldsm4(af[mt], ab + a_off + mt*16*A_STRIDE_B + kk*32);
#pragma unroll
            for (int pr = 0; pr < 2; ++pr)
                ldsm4(bf[pr], bb + b_off + pr*16*A_STRIDE_B + kk*32);
#pragma unroll
            for (int mt = 0; mt < 4; ++mt)
#pragma unroll
                for (int nt = 0; nt < 4; ++nt)
                    mma_bf(acc[mt][nt], af[mt],
                           bf[nt >> 1][(nt & 1)*2],
                           bf[nt >> 1][(nt & 1)*2 + 1]);
        }
    }
#undef LOAD_STAGE

    const int gr = lane >> 2, tg = lane & 3;
#pragma unroll
    for (int mt = 0; mt < 4; ++mt) {
        const int r0 = m0 + warp_m*64 + mt*16 + gr;
#pragma unroll
        for (int nt = 0; nt < 4; ++nt) {
            const int col = n0 + warp_n*32 + nt*8 + tg*2;
            const float2 bv = *reinterpret_cast<const float2*>(bias + col);
            const float v00 = acc[mt][nt][0] + bv.x;
            const float v01 = acc[mt][nt][1] + bv.y;
            const float v10 = acc[mt][nt][2] + bv.x;
            const float v11 = acc[mt][nt][3] + bv.y;
            if (MODE == 0) {
                store_qkv_h(r0,     col, v00, v01);
                store_qkv_h(r0 + 8, col, v10, v11);
            } else {
                *reinterpret_cast<float2*>(&outp[(size_t)r0*DIM + col]) =
                    make_float2(v00, v01);
                *reinterpret_cast<float2*>(&outp[(size_t)(r0+8)*DIM + col]) =
                    make_float2(v10, v11);
            }
        }
    }
}

// ---------------------------------------------------------------------------
// Tensor-core flash attention (fp16 mma.sync, fp32 softmax/accum).
// CTA: 128 q-rows, 8 warps x 16 rows. 32 key tiles of 64. Q frags resident.
// P reuses S C-frags as PV A-frags (no smem roundtrip). 3-buffer cp.async.
// Epilogue writes bf16 hi/lo split of O directly into g_os [hi|lo|hi].
// smem rows padded to 144B (72 halves) -> conflict-free ldmatrix.
// ---------------------------------------------------------------------------
#define ARS        144                    // row stride bytes
#define AQ_BYTES   (128*ARS)              // 18432
#define AKV_BYTES  (128*ARS)              // K(64)+V(64) per stage = 18432
#define ATTN_SMEM  (AQ_BYTES + 3*AKV_BYTES)   // 73728

__global__ __launch_bounds__(256, 2)
void attn_mma()
{
    extern __shared__ char smem[];
    const uint32_t sb = smem_u32(smem);
    const int tid  = threadIdx.x;
    const int lane = tid & 31, wid = tid >> 5;
    const int bh = blockIdx.y;
    const int n0 = blockIdx.x << 7;

    const __half* Qg = g_qh + (size_t)bh * SEQ * DH;
    const __half* Kg = g_kh + (size_t)bh * SEQ * DH;
    const __half* Vg = g_vh + (size_t)bh * SEQ * DH;

    // per-lane ldmatrix row/col pieces
    const int qr  = (lane & 7) + ((lane >> 3) & 1)*8;   // A / V-trans grouping
    const int qc8 = ((lane >> 4) & 1)*8;
    const int kr  = (lane & 7) + ((lane >> 4) & 1)*8;   // K (B non-trans) grouping
    const int kc8 = ((lane >> 3) & 1)*8;
    const int gid = lane >> 2, tg = lane & 3;
    const int i0 = wid*16;

    // ---- issue Q load (4 chunks/thread) + first two K/V stages ----
    {
        const int crow = tid >> 3, cq = (tid & 7)*8;
#pragma unroll
        for (int i = 0; i < 4; ++i)
            cp16(sb + (crow + 32*i)*ARS + cq*2, Qg + (size_t)(n0 + crow + 32*i)*DH + cq);
    }
    CP_COMMIT();

#define LOAD_KV(S, BUF) do {                                                  \
    const uint32_t kb = sb + AQ_BYTES + (BUF)*AKV_BYTES;                      \
    const int crow = tid >> 3, cq = (tid & 7)*8;                              \
    cp16(kb + crow*ARS + cq*2,        Kg + (size_t)((S)*64 + crow)*DH + cq);  \
    cp16(kb + (crow+32)*ARS + cq*2,   Kg + (size_t)((S)*64 + crow+32)*DH + cq);\
    cp16(kb + (crow+64)*ARS + cq*2,   Vg + (size_t)((S)*64 + crow)*DH + cq);  \
    cp16(kb + (crow+96)*ARS + cq*2,   Vg + (size_t)((S)*64 + crow+32)*DH + cq);\
} while (0)

    LOAD_KV(0, 0); CP_COMMIT();
    LOAD_KV(1, 1); CP_COMMIT();

    uint32_t qa[4][4];
    float oacc[8][4] = {};
    float m0r = -1e30f, m1r = -1e30f, l0r = 0.f, l1r = 0.f;

    for (int s = 0; s < 32; ++s) {
        if (s + 1 < 32) { CP_WAIT1(); } else { CP_WAIT0(); }
        __syncthreads();
        if (s == 0) {   // Q resident frags (once)
#pragma unroll
            for (int t = 0; t < 4; ++t)
                ldsm4(qa[t], sb + (i0 + qr)*ARS + (16*t + qc8)*2);
        }
        if (s + 2 < 32) { LOAD_KV(s + 2, (s + 2) % 3); CP_COMMIT(); }

        const uint32_t kb = sb + AQ_BYTES + (s % 3)*AKV_BYTES;
        const uint32_t vb = kb + 64*ARS;

        // ---- S = Qs @ K^T (fp32 acc) ----
        float sacc[8][4] = {};
#pragma unroll
        for (int t = 0; t < 4; ++t) {
#pragma unroll
            for (int p = 0; p < 4; ++p) {
                uint32_t kf[4];
                ldsm4(kf, kb + (16*p + kr)*ARS + (16*t + kc8)*2);
                mma_h(sacc[2*p],   qa[t][0], qa[t][1], qa[t][2], qa[t][3],
                      kf[0], kf[1]);
                mma_h(sacc[2*p+1], qa[t][0], qa[t][1], qa[t][2], qa[t][3],
                      kf[2], kf[3]);
            }
        }

        // ---- online softmax on fragments (rows gid, gid+8) ----
        float mx0 = -1e30f, mx1 = -1e30f;
#pragma unroll
        for (int nt = 0; nt < 8; ++nt) {
            mx0 = fmaxf(mx0, fmaxf(sacc[nt][0], sacc[nt][1]));
            mx1 = fmaxf(mx1, fmaxf(sacc[nt][2], sacc[nt][3]));
        }
        mx0 = fmaxf(mx0, __shfl_xor_sync(0xffffffffu, mx0, 1));
        mx0 = fmaxf(mx0, __shfl_xor_sync(0xffffffffu, mx0, 2));
        mx1 = fmaxf(mx1, __shfl_xor_sync(0xffffffffu, mx1, 1));
        mx1 = fmaxf(mx1, __shfl_xor_sync(0xffffffffu, mx1, 2));
        const float mn0 = fmaxf(m0r, mx0), mn1 = fmaxf(m1r, mx1);
        const float co0 = __expf(m0r - mn0), co1 = __expf(m1r - mn1);
        m0r = mn0; m1r = mn1;

        uint32_t ph0[8], ph1[8];
        float ps0 = 0.f, ps1 = 0.f;
#pragma unroll
        for (int nt = 0; nt < 8; ++nt) {
            float p0 = __expf(sacc[nt][0] - mn0);
            float p1 = __expf(sacc[nt][1] - mn0);
            float p2 = __expf(sacc[nt][2] - mn1);
            float p3 = __expf(sacc[nt][3] - mn1);
            ps0 += p0 + p1; ps1 += p2 + p3;
            __half2 h01 = __floats2half2_rn(p0, p1);
            __half2 h23 = __floats2half2_rn(p2, p3);
            ph0[nt] = *reinterpret_cast<uint32_t*>(&h01);
            ph1[nt] = *reinterpret_cast<uint32_t*>(&h23);
            oacc[nt][0] *= co0; oacc[nt][1] *= co0;
            oacc[nt][2] *= co1; oacc[nt][3] *= co1;
        }
        ps0 += __shfl_xor_sync(0xffffffffu, ps0, 1);
        ps0 += __shfl_xor_sync(0xffffffffu, ps0, 2);
        ps1 += __shfl_xor_sync(0xffffffffu, ps1, 1);
        ps1 += __shfl_xor_sync(0xffffffffu, ps1, 2);
        l0r = l0r*co0 + ps0;
        l1r = l1r*co1 + ps1;

        // ---- O += P @ V ----
#pragma unroll
        for (int t = 0; t < 4; ++t) {
            const uint32_t a0 = ph0[2*t],   a1 = ph1[2*t];
            const uint32_t a2 = ph0[2*t+1], a3 = ph1[2*t+1];
#pragma unroll
            for (int q = 0; q < 4; ++q) {
                uint32_t vf[4];
                ldsm4t(vf, vb + (16*t + qr)*ARS + (16*q + qc8)*2);
                mma_h(oacc[2*q],   a0, a1, a2, a3, vf[0], vf[1]);
                mma_h(oacc[2*q+1], a0, a1, a2, a3, vf[2], vf[3]);
            }
        }
    }
#undef LOAD_KV

    // ---- epilogue: normalize, bf16 hi/lo split straight into g_os ----
    const int b = bh >> 4, h = bh & 15;
    const int n_r0 = n0 + i0 + gid;
    const size_t tok0 = (size_t)(b*SEQ + n_r0)*KP;
    const size_t tok1 = (size_t)(b*SEQ + n_r0 + 8)*KP;
    const float iv0 = 1.0f / l0r, iv1 = 1.0f / l1r;
#pragma unroll
    for (int nt = 0; nt < 8; ++nt) {
        const int c = h*64 + nt*8 + tg*2;
        float o0 = oacc[nt][0]*iv0, o1 = oacc[nt][1]*iv0;
        float o2 = oacc[nt][2]*iv1, o3 = oacc[nt][3]*iv1;
        __nv_bfloat162 hi0, lo0, hi1, lo1;
        hi0.x = __float2bfloat16(o0); hi0.y = __float2bfloat16(o1);
        lo0.x = __float2bfloat16(o0 - __bfloat162float(hi0.x));
        lo0.y = __float2bfloat16(o1 - __bfloat162float(hi0.y));
        hi1.x = __float2bfloat16(o2); hi1.y = __float2bfloat16(o3);
        lo1.x = __float2bfloat16(o2 - __bfloat162float(hi1.x));
        lo1.y = __float2bfloat16(o3 - __bfloat162float(hi1.y));
        *reinterpret_cast<__nv_bfloat162*>(&g_os[tok0 + c])        = hi0;
        *reinterpret_cast<__nv_bfloat162*>(&g_os[tok0 + c + 1024]) = lo0;
        *reinterpret_cast<__nv_bfloat162*>(&g_os[tok0 + c + 2048]) = hi0;
        *reinterpret_cast<__nv_bfloat162*>(&g_os[tok1 + c])        = hi1;
        *reinterpret_cast<__nv_bfloat162*>(&g_os[tok1 + c + 1024]) = lo1;
        *reinterpret_cast<__nv_bfloat162*>(&g_os[tok1 + c + 2048]) = hi1;
    }
}

// ---------------------------------------------------------------------------
extern "C" void kernel_launch(void* const* d_in, const int* in_sizes, int n_in,
                              void* d_out, int out_size)
{
    const float* x      = (const float*)d_in[0];
    const float* qkv_w  = (const float*)d_in[1];
    const float* qkv_b  = (const float*)d_in[2];
    const float* proj_w = (const float*)d_in[3];
    const float* proj_b = (const float*)d_in[4];
    float* out = (float*)d_out;

    cudaFuncSetAttribute(attn_mma, cudaFuncAttributeMaxDynamicSharedMemorySize,
                         ATTN_SMEM);
    cudaFuncSetAttribute(gemm_mma<0>,
                         cudaFuncAttributeMaxDynamicSharedMemorySize, GSMEM);
    cudaFuncSetAttribute(gemm_mma<1>,
                         cudaFuncAttributeMaxDynamicSharedMemorySize, GSMEM);

    __nv_bfloat16 *xs_p, *os_p, *qw_p, *pw_p;
    cudaGetSymbolAddress((void**)&xs_p, g_xs);
    cudaGetSymbolAddress((void**)&os_p, g_os);
    cudaGetSymbolAddress((void**)&qw_p, g_qkvw);
    cudaGetSymbolAddress((void**)&pw_p, g_projw);

    dim3 blk(256);

    // 1) bf16 hi/lo splits of inputs/weights (K-concat trick)
    split_k1024<<<TOKENS, blk>>>(x,      xs_p, 0);
    split_k1024<<<QKV_N,  blk>>>(qkv_w,  qw_p, 1);
    split_k1024<<<DIM,    blk>>>(proj_w, pw_p, 1);

    // 2) QKV projection (split-bf16 mma) -> fp16 q(0.125x)/k/v
    gemm_mma<0><<<dim3(QKV_N/128, TOKENS/128), blk, GSMEM>>>(
        xs_p, qw_p, qkv_b, nullptr);

    // 3) Tensor-core flash attention -> g_os (bf16 split, fused)
    attn_mma<<<dim3(SEQ/128, BATCH*NHEADS), blk, ATTN_SMEM>>>();

    // 4) Output projection (split-bf16 mma) -> d_out
    gemm_mma<1><<<dim3(DIM/128, TOKENS/128), blk, GSMEM>>>(
        os_p, pw_p, proj_b, out);
}

// round 12
// speedup vs baseline: 5.3278x; 1.0471x over previous
#include <cuda_runtime.h>
#include <cuda_bf16.h>
#include <cuda_fp16.h>
#include <cstdint>

#define DIM    1024
#define BATCH  2
#define SEQ    2048
#define NHEADS 16
#define DH     64
#define TOKENS (BATCH*SEQ)      // 4096
#define QKV_N  (3*DIM)          // 3072
#define KP     3072             // split K' = 3*1024

// ---------------- scratch (__device__ globals; allocation-free rule) --------
__device__ __align__(16) __half g_qh[BATCH*NHEADS*SEQ*DH]; // fp16 q (pre-scaled 0.125)
__device__ __align__(16) __half g_kh[BATCH*NHEADS*SEQ*DH]; // fp16 k
__device__ __align__(16) __half g_vh[BATCH*NHEADS*SEQ*DH]; // fp16 v

__device__ __align__(16) __nv_bfloat16 g_xs   [TOKENS*KP]; // x split   [hi|lo|hi]
__device__ __align__(16) __nv_bfloat16 g_os   [TOKENS*KP]; // attn out  [hi|lo|hi]
__device__ __align__(16) __nv_bfloat16 g_qkvw [QKV_N*KP];  // qkv_w     [hi|hi|lo]
__device__ __align__(16) __nv_bfloat16 g_projw[DIM*KP];    // proj_w    [hi|hi|lo]

// ---------------------------------------------------------------------------
// PTX helpers (all plain sm_80-era PTX; valid on compute_103)
// ---------------------------------------------------------------------------
__device__ __forceinline__ uint32_t smem_u32(const void* p) {
    uint32_t a;
    asm("{ .reg .u64 t; cvta.to.shared.u64 t, %1; cvt.u32.u64 %0, t; }"
        : "=r"(a) : "l"(p));
    return a;
}
__device__ __forceinline__ void cp16(uint32_t dst, const void* src) {
    asm volatile("cp.async.cg.shared.global [%0], [%1], 16;"
                 :: "r"(dst), "l"(src) : "memory");
}
#define CP_COMMIT() asm volatile("cp.async.commit_group;" ::: "memory")
#define CP_WAIT0()  asm volatile("cp.async.wait_group 0;"  ::: "memory")
#define CP_WAIT1()  asm volatile("cp.async.wait_group 1;"  ::: "memory")
#define CP_WAIT2()  asm volatile("cp.async.wait_group 2;"  ::: "memory")
// Exact stage-s completion wait under always-commit discipline:
#define CP_WAIT_STAGE(S, NS) do {                  \
    if      ((S) + 2 < (NS)) CP_WAIT2();           \
    else if ((S) + 1 < (NS)) CP_WAIT1();           \
    else                     CP_WAIT0();           \
} while (0)

__device__ __forceinline__ void ldsm4(uint32_t* r, uint32_t a) {
    asm volatile("ldmatrix.sync.aligned.m8n8.x4.shared.b16 {%0,%1,%2,%3}, [%4];"
                 : "=r"(r[0]), "=r"(r[1]), "=r"(r[2]), "=r"(r[3]) : "r"(a));
}
__device__ __forceinline__ void ldsm4t(uint32_t* r, uint32_t a) {
    asm volatile("ldmatrix.sync.aligned.m8n8.x4.trans.shared.b16 {%0,%1,%2,%3}, [%4];"
                 : "=r"(r[0]), "=r"(r[1]), "=r"(r[2]), "=r"(r[3]) : "r"(a));
}
__device__ __forceinline__ void mma_bf(float* c, const uint32_t* a,
                                       uint32_t b0, uint32_t b1) {
    asm volatile(
        "mma.sync.aligned.m16n8k16.row.col.f32.bf16.bf16.f32 "
        "{%0,%1,%2,%3}, {%4,%5,%6,%7}, {%8,%9}, {%0,%1,%2,%3};"
        : "+f"(c[0]), "+f"(c[1]), "+f"(c[2]), "+f"(c[3])
        : "r"(a[0]), "r"(a[1]), "r"(a[2]), "r"(a[3]), "r"(b0), "r"(b1));
}
__device__ __forceinline__ void mma_h(float* c, uint32_t a0, uint32_t a1,
                                      uint32_t a2, uint32_t a3,
                                      uint32_t b0, uint32_t b1) {
    asm volatile(
        "mma.sync.aligned.m16n8k16.row.col.f32.f16.f16.f32 "
        "{%0,%1,%2,%3}, {%4,%5,%6,%7}, {%8,%9}, {%0,%1,%2,%3};"
        : "+f"(c[0]), "+f"(c[1]), "+f"(c[2]), "+f"(c[3])
        : "r"(a0), "r"(a1), "r"(a2), "r"(a3), "r"(b0), "r"(b1));
}

// ---------------------------------------------------------------------------
// split_k1024: fp32 [rows,1024] -> bf16 [rows,3072].
// bpat=0 (A side): [hi | lo | hi] ; bpat=1 (B side): [hi | hi | lo]
// ---------------------------------------------------------------------------
__global__ __launch_bounds__(256)
void split_k1024(const float* __restrict__ src, __nv_bfloat16* __restrict__ dst,
                 int bpat)
{
    const int r = blockIdx.x;
    const int k = threadIdx.x << 2;
    float4 v = *reinterpret_cast<const float4*>(src + (size_t)r*1024 + k);
    float f[4] = {v.x, v.y, v.z, v.w};
    __nv_bfloat16 hi[4], lo[4];
#pragma unroll
    for (int i = 0; i < 4; ++i) {
        hi[i] = __float2bfloat16(f[i]);
        lo[i] = __float2bfloat16(f[i] - __bfloat162float(hi[i]));
    }
    __nv_bfloat16* d0 = dst + (size_t)r*KP + k;
    __nv_bfloat162 h01, h23, l01, l23;
    h01.x = hi[0]; h01.y = hi[1]; h23.x = hi[2]; h23.y = hi[3];
    l01.x = lo[0]; l01.y = lo[1]; l23.x = lo[2]; l23.y = lo[3];
    reinterpret_cast<__nv_bfloat162*>(d0)[0] = h01;
    reinterpret_cast<__nv_bfloat162*>(d0)[1] = h23;
    __nv_bfloat16* d1 = d0 + 1024;
    __nv_bfloat16* d2 = d0 + 2048;
    if (bpat) {
        reinterpret_cast<__nv_bfloat162*>(d1)[0] = h01;
        reinterpret_cast<__nv_bfloat162*>(d1)[1] = h23;
        reinterpret_cast<__nv_bfloat162*>(d2)[0] = l01;
        reinterpret_cast<__nv_bfloat162*>(d2)[1] = l23;
    } else {
        reinterpret_cast<__nv_bfloat162*>(d1)[0] = l01;
        reinterpret_cast<__nv_bfloat162*>(d1)[1] = l23;
        reinterpret_cast<__nv_bfloat162*>(d2)[0] = h01;
        reinterpret_cast<__nv_bfloat162*>(d2)[1] = h23;
    }
}

// ---------------------------------------------------------------------------
// mma.sync GEMM: C = A'[M,K'] @ W'[Nout,K']^T + bias (fp32 acc).
// BM=BN=128, BK=32 bf16, 8 warps (2m x 4n). 4-deep cp.async ring, 3 loads in
// flight, exact tail waits.
// MODE 0: write q/k/v as fp16 to g_qh/g_kh/g_vh (q pre-scaled by 0.125).
// MODE 1: write fp32 outp[m*DIM + j].
// ---------------------------------------------------------------------------
#define BK         32
#define A_STRIDE_B 80
#define STAGE_OPER (128*A_STRIDE_B)
#define STAGE_B    (2*STAGE_OPER)          // 20480
#define GNBUF      4
#define GSMEM      (GNBUF*STAGE_B)         // 81920
#define NSTG       (KP/BK)                 // 96

__device__ __forceinline__ void store_qkv_h(int m, int col, float x, float y) {
    const int c3 = col >> 10;
    const int h  = (col >> 6) & 15, d = col & 63;
    const int b  = m >> 11,  n = m & 2047;
    const float sc = (c3 == 0) ? 0.125f : 1.0f;
    __half* p = (c3 == 0) ? g_qh : (c3 == 1) ? g_kh : g_vh;
    *reinterpret_cast<__half2*>(
        &p[((size_t)((b << 4) + h)*SEQ + n)*DH + d]) =
        __floats2half2_rn(x*sc, y*sc);
}

template<int MODE>
__global__ __launch_bounds__(256, 2)
void gemm_mma(const __nv_bfloat16* __restrict__ Ag,
              const __nv_bfloat16* __restrict__ Wg,
              const float* __restrict__ bias, float* __restrict__ outp)
{
    extern __shared__ char smem[];
    const uint32_t sbase = smem_u32(smem);
    const int tid  = threadIdx.x;
    const int lane = tid & 31, wid = tid >> 5;
    const int warp_m = wid >> 2, warp_n = wid & 3;
    const int m0 = blockIdx.y << 7, n0 = blockIdx.x << 7;

    const int rr = tid >> 2;
    const int kc = tid & 3;

    const __nv_bfloat16* Ab = Ag + (size_t)m0*KP + kc*8;
    const __nv_bfloat16* Wb = Wg + (size_t)n0*KP + kc*8;

#define LOAD_STAGE(S, BUF) do {                                               \
    const uint32_t sa = sbase + (BUF)*STAGE_B;                                \
    const uint32_t sw = sa + STAGE_OPER;                                      \
    const size_t ko = (size_t)(S)*BK;                                         \
    cp16(sa + rr*A_STRIDE_B + kc*16,        Ab + (size_t)rr*KP + ko);         \
    cp16(sa + (rr+64)*A_STRIDE_B + kc*16,   Ab + (size_t)(rr+64)*KP + ko);    \
    cp16(sw + rr*A_STRIDE_B + kc*16,        Wb + (size_t)rr*KP + ko);         \
    cp16(sw + (rr+64)*A_STRIDE_B + kc*16,   Wb + (size_t)(rr+64)*KP + ko);    \
} while (0)

    const uint32_t a_off = (uint32_t)((warp_m*64 + (lane & 15))*A_STRIDE_B
                                      + (lane >> 4)*16);
    const uint32_t b_off = (uint32_t)((warp_n*32 + (lane & 7)
                                      + ((lane >> 4) & 1)*8)*A_STRIDE_B
                                      + ((lane >> 3) & 1)*16);

    float acc[4][4][4] = {};

    LOAD_STAGE(0, 0); CP_COMMIT();
    LOAD_STAGE(1, 1); CP_COMMIT();
    LOAD_STAGE(2, 2); CP_COMMIT();

    for (int s = 0; s < NSTG; ++s) {
        CP_WAIT_STAGE(s, NSTG);          // stage s resident (exact at tail)
        __syncthreads();                  // buffer (s-1)&3 fully consumed
        if (s + 3 < NSTG) LOAD_STAGE(s + 3, (s + 3) & 3);
        CP_COMMIT();                      // always commit (uniform group count)

        const uint32_t ab = sbase + (s & 3)*STAGE_B;
        const uint32_t bb = ab + STAGE_OPER;
#pragma unroll
        for (int kk = 0; kk < 2; ++kk) {
            uint32_t af[4][4], bf[2][4];
#pragma unroll
            for (int mt = 0; mt < 4; ++mt)
                ldsm4(af[mt], ab + a_off + mt*16*A_STRIDE_B + kk*32);
#pragma unroll
            for (int pr = 0; pr < 2; ++pr)
                ldsm4(bf[pr], bb + b_off + pr*16*A_STRIDE_B + kk*32);
#pragma unroll
            for (int mt = 0; mt < 4; ++mt)
#pragma unroll
                for (int nt = 0; nt < 4; ++nt)
                    mma_bf(acc[mt][nt], af[mt],
                           bf[nt >> 1][(nt & 1)*2],
                           bf[nt >> 1][(nt & 1)*2 + 1]);
        }
    }
#undef LOAD_STAGE

    const int gr = lane >> 2, tg = lane & 3;
#pragma unroll
    for (int mt = 0; mt < 4; ++mt) {
        const int r0 = m0 + warp_m*64 + mt*16 + gr;
#pragma unroll
        for (int nt = 0; nt < 4; ++nt) {
            const int col = n0 + warp_n*32 + nt*8 + tg*2;
            const float2 bv = *reinterpret_cast<const float2*>(bias + col);
            const float v00 = acc[mt][nt][0] + bv.x;
            const float v01 = acc[mt][nt][1] + bv.y;
            const float v10 = acc[mt][nt][2] + bv.x;
            const float v11 = acc[mt][nt][3] + bv.y;
            if (MODE == 0) {
                store_qkv_h(r0,     col, v00, v01);
                store_qkv_h(r0 + 8, col, v10, v11);
            } else {
                *reinterpret_cast<float2*>(&outp[(size_t)r0*DIM + col]) =
                    make_float2(v00, v01);
                *reinterpret_cast<float2*>(&outp[(size_t)(r0+8)*DIM + col]) =
                    make_float2(v10, v11);
            }
        }
    }
}

// ---------------------------------------------------------------------------
// Tensor-core flash attention (fp16 mma.sync, fp32 softmax/accum).
// CTA: 128 q-rows, 8 warps x 16 rows. 32 key tiles of 64. Q frags resident.
// P reuses S C-frags as PV A-frags. 4-deep cp.async KV ring (3 in flight).
// Epilogue writes bf16 hi/lo split of O directly into g_os [hi|lo|hi].
// ---------------------------------------------------------------------------
#define ARS        144                    // row stride bytes
#define AQ_BYTES   (128*ARS)              // 18432
#define AKV_BYTES  (128*ARS)              // K(64)+V(64) per stage = 18432
#define ANBUF      4
#define ATTN_SMEM  (AQ_BYTES + ANBUF*AKV_BYTES)   // 92160
#define NSTG32     32

__global__ __launch_bounds__(256, 2)
void attn_mma()
{
    extern __shared__ char smem[];
    const uint32_t sb = smem_u32(smem);
    const int tid  = threadIdx.x;
    const int lane = tid & 31, wid = tid >> 5;
    const int bh = blockIdx.y;
    const int n0 = blockIdx.x << 7;

    const __half* Qg = g_qh + (size_t)bh * SEQ * DH;
    const __half* Kg = g_kh + (size_t)bh * SEQ * DH;
    const __half* Vg = g_vh + (size_t)bh * SEQ * DH;

    const int qr  = (lane & 7) + ((lane >> 3) & 1)*8;   // A / V-trans grouping
    const int qc8 = ((lane >> 4) & 1)*8;
    const int kr  = (lane & 7) + ((lane >> 4) & 1)*8;   // K (B non-trans)
    const int kc8 = ((lane >> 3) & 1)*8;
    const int gid = lane >> 2, tg = lane & 3;
    const int i0 = wid*16;

    // ---- Q load (group 0) + first three K/V stages ----
    {
        const int crow = tid >> 3, cq = (tid & 7)*8;
#pragma unroll
        for (int i = 0; i < 4; ++i)
            cp16(sb + (crow + 32*i)*ARS + cq*2,
                 Qg + (size_t)(n0 + crow + 32*i)*DH + cq);
    }
    CP_COMMIT();

#define LOAD_KV(S, BUF) do {                                                  \
    const uint32_t kb = sb + AQ_BYTES + (BUF)*AKV_BYTES;                      \
    const int crow = tid >> 3, cq = (tid & 7)*8;                              \
    cp16(kb + crow*ARS + cq*2,        Kg + (size_t)((S)*64 + crow)*DH + cq);  \
    cp16(kb + (crow+32)*ARS + cq*2,   Kg + (size_t)((S)*64 + crow+32)*DH + cq);\
    cp16(kb + (crow+64)*ARS + cq*2,   Vg + (size_t)((S)*64 + crow)*DH + cq);  \
    cp16(kb + (crow+96)*ARS + cq*2,   Vg + (size_t)((S)*64 + crow+32)*DH + cq);\
} while (0)

    LOAD_KV(0, 0); CP_COMMIT();
    LOAD_KV(1, 1); CP_COMMIT();
    LOAD_KV(2, 2); CP_COMMIT();

    uint32_t qa[4][4];
    float oacc[8][4] = {};
    float m0r = -1e30f, m1r = -1e30f, l0r = 0.f, l1r = 0.f;

    for (int s = 0; s < NSTG32; ++s) {
        CP_WAIT_STAGE(s, NSTG32);   // KV stage s resident (Q also done at s=0)
        __syncthreads();
        if (s == 0) {   // Q resident frags (once)
#pragma unroll
            for (int t = 0; t < 4; ++t)
                ldsm4(qa[t], sb + (i0 + qr)*ARS + (16*t + qc8)*2);
        }
        if (s + 3 < NSTG32) LOAD_KV(s + 3, (s + 3) & 3);
        CP_COMMIT();                // always commit (uniform group count)

        const uint32_t kb = sb + AQ_BYTES + (s & 3)*AKV_BYTES;
        const uint32_t vb = kb + 64*ARS;

        // ---- S = Qs @ K^T (fp32 acc) ----
        float sacc[8][4] = {};
#pragma unroll
        for (int t = 0; t < 4; ++t) {
#pragma unroll
            for (int p = 0; p < 4; ++p) {
                uint32_t kf[4];
                ldsm4(kf, kb + (16*p + kr)*ARS + (16*t + kc8)*2);
                mma_h(sacc[2*p],   qa[t][0], qa[t][1], qa[t][2], qa[t][3],
                      kf[0], kf[1]);
                mma_h(sacc[2*p+1], qa[t][0], qa[t][1], qa[t][2], qa[t][3],
                      kf[2], kf[3]);
            }
        }

        // ---- online softmax on fragments (rows gid, gid+8) ----
        float mx0 = -1e30f, mx1 = -1e30f;
#pragma unroll
        for (int nt = 0; nt < 8; ++nt) {
            mx0 = fmaxf(mx0, fmaxf(sacc[nt][0], sacc[nt][1]));
            mx1 = fmaxf(mx1, fmaxf(sacc[nt][2], sacc[nt][3]));
        }
        mx0 = fmaxf(mx0, __shfl_xor_sync(0xffffffffu, mx0, 1));
        mx0 = fmaxf(mx0, __shfl_xor_sync(0xffffffffu, mx0, 2));
        mx1 = fmaxf(mx1, __shfl_xor_sync(0xffffffffu, mx1, 1));
        mx1 = fmaxf(mx1, __shfl_xor_sync(0xffffffffu, mx1, 2));
        const float mn0 = fmaxf(m0r, mx0), mn1 = fmaxf(m1r, mx1);
        const float co0 = __expf(m0r - mn0), co1 = __expf(m1r - mn1);
        m0r = mn0; m1r = mn1;

        uint32_t ph0[8], ph1[8];
        float ps0 = 0.f, ps1 = 0.f;
#pragma unroll
        for (int nt = 0; nt < 8; ++nt) {
            float p0 = __expf(sacc[nt][0] - mn0);
            float p1 = __expf(sacc[nt][1] - mn0);
            float p2 = __expf(sacc[nt][2] - mn1);
            float p3 = __expf(sacc[nt][3] - mn1);
            ps0 += p0 + p1; ps1 += p2 + p3;
            __half2 h01 = __floats2half2_rn(p0, p1);
            __half2 h23 = __floats2half2_rn(p2, p3);
            ph0[nt] = *reinterpret_cast<uint32_t*>(&h01);
            ph1[nt] = *reinterpret_cast<uint32_t*>(&h23);
            oacc[nt][0] *= co0; oacc[nt][1] *= co0;
            oacc[nt][2] *= co1; oacc[nt][3] *= co1;
        }
        ps0 += __shfl_xor_sync(0xffffffffu, ps0, 1);
        ps0 += __shfl_xor_sync(0xffffffffu, ps0, 2);
        ps1 += __shfl_xor_sync(0xffffffffu, ps1, 1);
        ps1 += __shfl_xor_sync(0xffffffffu, ps1, 2);
        l0r = l0r*co0 + ps0;
        l1r = l1r*co1 + ps1;

        // ---- O += P @ V ----
#pragma unroll
        for (int t = 0; t < 4; ++t) {
            const uint32_t a0 = ph0[2*t],   a1 = ph1[2*t];
            const uint32_t a2 = ph0[2*t+1], a3 = ph1[2*t+1];
#pragma unroll
            for (int q = 0; q < 4; ++q) {
                uint32_t vf[4];
                ldsm4t(vf, vb + (16*t + qr)*ARS + (16*q + qc8)*2);
                mma_h(oacc[2*q],   a0, a1, a2, a3, vf[0], vf[1]);
                mma_h(oacc[2*q+1], a0, a1, a2, a3, vf[2], vf[3]);
            }
        }
    }
#undef LOAD_KV

    // ---- epilogue: normalize, bf16 hi/lo split straight into g_os ----
    const int b = bh >> 4, h = bh & 15;
    const int n_r0 = n0 + i0 + gid;
    const size_t tok0 = (size_t)(b*SEQ + n_r0)*KP;
    const size_t tok1 = (size_t)(b*SEQ + n_r0 + 8)*KP;
    const float iv0 = 1.0f / l0r, iv1 = 1.0f / l1r;
#pragma unroll
    for (int nt = 0; nt < 8; ++nt) {
        const int c = h*64 + nt*8 + tg*2;
        float o0 = oacc[nt][0]*iv0, o1 = oacc[nt][1]*iv0;
        float o2 = oacc[nt][2]*iv1, o3 = oacc[nt][3]*iv1;
        __nv_bfloat162 hi0, lo0, hi1, lo1;
        hi0.x = __float2bfloat16(o0); hi0.y = __float2bfloat16(o1);
        lo0.x = __float2bfloat16(o0 - __bfloat162float(hi0.x));
        lo0.y = __float2bfloat16(o1 - __bfloat162float(hi0.y));
        hi1.x = __float2bfloat16(o2); hi1.y = __float2bfloat16(o3);
        lo1.x = __float2bfloat16(o2 - __bfloat162float(hi1.x));
        lo1.y = __float2bfloat16(o3 - __bfloat162float(hi1.y));
        *reinterpret_cast<__nv_bfloat162*>(&g_os[tok0 + c])        = hi0;
        *reinterpret_cast<__nv_bfloat162*>(&g_os[tok0 + c + 1024]) = lo0;
        *reinterpret_cast<__nv_bfloat162*>(&g_os[tok0 + c + 2048]) = hi0;
        *reinterpret_cast<__nv_bfloat162*>(&g_os[tok1 + c])        = hi1;
        *reinterpret_cast<__nv_bfloat162*>(&g_os[tok1 + c + 1024]) = lo1;
        *reinterpret_cast<__nv_bfloat162*>(&g_os[tok1 + c + 2048]) = hi1;
    }
}

// ---------------------------------------------------------------------------
extern "C" void kernel_launch(void* const* d_in, const int* in_sizes, int n_in,
                              void* d_out, int out_size)
{
    const float* x      = (const float*)d_in[0];
    const float* qkv_w  = (const float*)d_in[1];
    const float* qkv_b  = (const float*)d_in[2];
    const float* proj_w = (const float*)d_in[3];
    const float* proj_b = (const float*)d_in[4];
    float* out = (float*)d_out;

    cudaFuncSetAttribute(attn_mma, cudaFuncAttributeMaxDynamicSharedMemorySize,
                         ATTN_SMEM);
    cudaFuncSetAttribute(gemm_mma<0>,
                         cudaFuncAttributeMaxDynamicSharedMemorySize, GSMEM);
    cudaFuncSetAttribute(gemm_mma<1>,
                         cudaFuncAttributeMaxDynamicSharedMemorySize, GSMEM);

    __nv_bfloat16 *xs_p, *os_p, *qw_p, *pw_p;
    cudaGetSymbolAddress((void**)&xs_p, g_xs);
    cudaGetSymbolAddress((void**)&os_p, g_os);
    cudaGetSymbolAddress((void**)&qw_p, g_qkvw);
    cudaGetSymbolAddress((void**)&pw_p, g_projw);

    dim3 blk(256);

    // 1) bf16 hi/lo splits of inputs/weights (K-concat trick)
    split_k1024<<<TOKENS, blk>>>(x,      xs_p, 0);
    split_k1024<<<QKV_N,  blk>>>(qkv_w,  qw_p, 1);
    split_k1024<<<DIM,    blk>>>(proj_w, pw_p, 1);

    // 2) QKV projection (split-bf16 mma) -> fp16 q(0.125x)/k/v
    gemm_mma<0><<<dim3(QKV_N/128, TOKENS/128), blk, GSMEM>>>(
        xs_p, qw_p, qkv_b, nullptr);

    // 3) Tensor-core flash attention -> g_os (bf16 split, fused)
    attn_mma<<<dim3(SEQ/128, BATCH*NHEADS), blk, ATTN_SMEM>>>();

    // 4) Output projection (split-bf16 mma) -> d_out
    gemm_mma<1><<<dim3(DIM/128, TOKENS/128), blk, GSMEM>>>(
        os_p, pw_p, proj_b, out);
}

// round 13
// speedup vs baseline: 9.8699x; 1.8525x over previous
#include <cuda_runtime.h>
#include <cuda_fp16.h>
#include <cstdint>

#define DIM    1024
#define BATCH  2
#define SEQ    2048
#define NHEADS 16
#define DH     64
#define TOKENS (BATCH*SEQ)      // 4096
#define QKV_N  (3*DIM)          // 3072
#define KDIM   1024             // GEMM reduction dim (no split concat)

// ---------------- scratch (__device__ globals; allocation-free rule) --------
__device__ __align__(16) __half g_qh[BATCH*NHEADS*SEQ*DH]; // fp16 q (pre-scaled 0.125)
__device__ __align__(16) __half g_kh[BATCH*NHEADS*SEQ*DH]; // fp16 k
__device__ __align__(16) __half g_vh[BATCH*NHEADS*SEQ*DH]; // fp16 v

__device__ __align__(16) __half g_xh   [TOKENS*KDIM];      // x      fp16
__device__ __align__(16) __half g_oh   [TOKENS*DIM];       // attn O fp16 [b,n,c]
__device__ __align__(16) __half g_qkvwh[QKV_N*KDIM];       // qkv_w  fp16
__device__ __align__(16) __half g_projwh[DIM*KDIM];        // proj_w fp16

// ---------------------------------------------------------------------------
// PTX helpers (plain sm_80-era PTX; valid on compute_103)
// ---------------------------------------------------------------------------
__device__ __forceinline__ uint32_t smem_u32(const void* p) {
    uint32_t a;
    asm("{ .reg .u64 t; cvta.to.shared.u64 t, %1; cvt.u32.u64 %0, t; }"
        : "=r"(a) : "l"(p));
    return a;
}
__device__ __forceinline__ void cp16(uint32_t dst, const void* src) {
    asm volatile("cp.async.cg.shared.global [%0], [%1], 16;"
                 :: "r"(dst), "l"(src) : "memory");
}
#define CP_COMMIT() asm volatile("cp.async.commit_group;" ::: "memory")
#define CP_WAIT0()  asm volatile("cp.async.wait_group 0;"  ::: "memory")
#define CP_WAIT1()  asm volatile("cp.async.wait_group 1;"  ::: "memory")
#define CP_WAIT2()  asm volatile("cp.async.wait_group 2;"  ::: "memory")
#define CP_WAIT_STAGE(S, NS) do {                  \
    if      ((S) + 2 < (NS)) CP_WAIT2();           \
    else if ((S) + 1 < (NS)) CP_WAIT1();           \
    else                     CP_WAIT0();           \
} while (0)

__device__ __forceinline__ void ldsm4(uint32_t* r, uint32_t a) {
    asm volatile("ldmatrix.sync.aligned.m8n8.x4.shared.b16 {%0,%1,%2,%3}, [%4];"
                 : "=r"(r[0]), "=r"(r[1]), "=r"(r[2]), "=r"(r[3]) : "r"(a));
}
__device__ __forceinline__ void ldsm4t(uint32_t* r, uint32_t a) {
    asm volatile("ldmatrix.sync.aligned.m8n8.x4.trans.shared.b16 {%0,%1,%2,%3}, [%4];"
                 : "=r"(r[0]), "=r"(r[1]), "=r"(r[2]), "=r"(r[3]) : "r"(a));
}
__device__ __forceinline__ void mma_h(float* c, uint32_t a0, uint32_t a1,
                                      uint32_t a2, uint32_t a3,
                                      uint32_t b0, uint32_t b1) {
    asm volatile(
        "mma.sync.aligned.m16n8k16.row.col.f32.f16.f16.f32 "
        "{%0,%1,%2,%3}, {%4,%5,%6,%7}, {%8,%9}, {%0,%1,%2,%3};"
        : "+f"(c[0]), "+f"(c[1]), "+f"(c[2]), "+f"(c[3])
        : "r"(a0), "r"(a1), "r"(a2), "r"(a3), "r"(b0), "r"(b1));
}

// ---------------------------------------------------------------------------
// tofp16: fp32 -> fp16 convert (float4 -> 8B packed), grid-stride free sizing
// ---------------------------------------------------------------------------
__global__ __launch_bounds__(256)
void tofp16(const float* __restrict__ src, __half* __restrict__ dst, int n4)
{
    const int i = blockIdx.x*256 + threadIdx.x;
    if (i >= n4) return;
    float4 v = reinterpret_cast<const float4*>(src)[i];
    __half2 h01 = __floats2half2_rn(v.x, v.y);
    __half2 h23 = __floats2half2_rn(v.z, v.w);
    uint2 pk;
    pk.x = *reinterpret_cast<uint32_t*>(&h01);
    pk.y = *reinterpret_cast<uint32_t*>(&h23);
    reinterpret_cast<uint2*>(dst)[i] = pk;
}

// ---------------------------------------------------------------------------
// mma.sync fp16 GEMM: C = A[M,1024] @ W[Nout,1024]^T + bias (fp32 acc).
// BM=BN=128, BK=32, 8 warps (2m x 4n). 4-deep cp.async ring, exact tail waits.
// MODE 0: write q/k/v as fp16 to g_qh/g_kh/g_vh (q pre-scaled by 0.125).
// MODE 1: write fp32 outp[m*DIM + j].
// ---------------------------------------------------------------------------
#define BK         32
#define A_STRIDE_B 80
#define STAGE_OPER (128*A_STRIDE_B)
#define STAGE_B    (2*STAGE_OPER)          // 20480
#define GSMEM      (4*STAGE_B)             // 81920
#define NSTG       (KDIM/BK)               // 32

__device__ __forceinline__ void store_qkv_h(int m, int col, float x, float y) {
    const int c3 = col >> 10;
    const int h  = (col >> 6) & 15, d = col & 63;
    const int b  = m >> 11,  n = m & 2047;
    const float sc = (c3 == 0) ? 0.125f : 1.0f;
    __half* p = (c3 == 0) ? g_qh : (c3 == 1) ? g_kh : g_vh;
    *reinterpret_cast<__half2*>(
        &p[((size_t)((b << 4) + h)*SEQ + n)*DH + d]) =
        __floats2half2_rn(x*sc, y*sc);
}

template<int MODE>
__global__ __launch_bounds__(256, 2)
void gemm_mma(const __half* __restrict__ Ag, const __half* __restrict__ Wg,
              const float* __restrict__ bias, float* __restrict__ outp)
{
    extern __shared__ char smem[];
    const uint32_t sbase = smem_u32(smem);
    const int tid  = threadIdx.x;
    const int lane = tid & 31, wid = tid >> 5;
    const int warp_m = wid >> 2, warp_n = wid & 3;
    const int m0 = blockIdx.y << 7, n0 = blockIdx.x << 7;

    const int rr = tid >> 2;
    const int kc = tid & 3;

    const __half* Ab = Ag + (size_t)m0*KDIM + kc*8;
    const __half* Wb = Wg + (size_t)n0*KDIM + kc*8;

#define LOAD_STAGE(S, BUF) do {                                               \
    const uint32_t sa = sbase + (BUF)*STAGE_B;                                \
    const uint32_t sw = sa + STAGE_OPER;                                      \
    const size_t ko = (size_t)(S)*BK;                                         \
    cp16(sa + rr*A_STRIDE_B + kc*16,        Ab + (size_t)rr*KDIM + ko);       \
    cp16(sa + (rr+64)*A_STRIDE_B + kc*16,   Ab + (size_t)(rr+64)*KDIM + ko);  \
    cp16(sw + rr*A_STRIDE_B + kc*16,        Wb + (size_t)rr*KDIM + ko);       \
    cp16(sw + (rr+64)*A_STRIDE_B + kc*16,   Wb + (size_t)(rr+64)*KDIM + ko);  \
} while (0)

    const uint32_t a_off = (uint32_t)((warp_m*64 + (lane & 15))*A_STRIDE_B
                                      + (lane >> 4)*16);
    const uint32_t b_off = (uint32_t)((warp_n*32 + (lane & 7)
                                      + ((lane >> 4) & 1)*8)*A_STRIDE_B
                                      + ((lane >> 3) & 1)*16);

    float acc[4][4][4] = {};

    LOAD_STAGE(0, 0); CP_COMMIT();
    LOAD_STAGE(1, 1); CP_COMMIT();
    LOAD_STAGE(2, 2); CP_COMMIT();

    for (int s = 0; s < NSTG; ++s) {
        CP_WAIT_STAGE(s, NSTG);
        __syncthreads();
        if (s + 3 < NSTG) LOAD_STAGE(s + 3, (s + 3) & 3);
        CP_COMMIT();

        const uint32_t ab = sbase + (s & 3)*STAGE_B;
        const uint32_t bb = ab + STAGE_OPER;
#pragma unroll
        for (int kk = 0; kk < 2; ++kk) {
            uint32_t af[4][4], bf[2][4];
#pragma unroll
            for (int mt = 0; mt < 4; ++mt)
                ldsm4(af[mt], ab + a_off + mt*16*A_STRIDE_B + kk*32);
#pragma unroll
            for (int pr = 0; pr < 2; ++pr)
                ldsm4(bf[pr], bb + b_off + pr*16*A_STRIDE_B + kk*32);
#pragma unroll
            for (int mt = 0; mt < 4; ++mt)
#pragma unroll
                for (int nt = 0; nt < 4; ++nt)
                    mma_h(acc[mt][nt],
                          af[mt][0], af[mt][1], af[mt][2], af[mt][3],
                          bf[nt >> 1][(nt & 1)*2],
                          bf[nt >> 1][(nt & 1)*2 + 1]);
        }
    }
#undef LOAD_STAGE

    const int gr = lane >> 2, tg = lane & 3;
#pragma unroll
    for (int mt = 0; mt < 4; ++mt) {
        const int r0 = m0 + warp_m*64 + mt*16 + gr;
#pragma unroll
        for (int nt = 0; nt < 4; ++nt) {
            const int col = n0 + warp_n*32 + nt*8 + tg*2;
            const float2 bv = *reinterpret_cast<const float2*>(bias + col);
            const float v00 = acc[mt][nt][0] + bv.x;
            const float v01 = acc[mt][nt][1] + bv.y;
            const float v10 = acc[mt][nt][2] + bv.x;
            const float v11 = acc[mt][nt][3] + bv.y;
            if (MODE == 0) {
                store_qkv_h(r0,     col, v00, v01);
                store_qkv_h(r0 + 8, col, v10, v11);
            } else {
                *reinterpret_cast<float2*>(&outp[(size_t)r0*DIM + col]) =
                    make_float2(v00, v01);
                *reinterpret_cast<float2*>(&outp[(size_t)(r0+8)*DIM + col]) =
                    make_float2(v10, v11);
            }
        }
    }
}

// ---------------------------------------------------------------------------
// Tensor-core flash attention (fp16 mma.sync, fp32 softmax/accum).
// CTA: 128 q-rows, 8 warps x 16 rows. 32 key tiles of 64. Q frags resident.
// P reuses S C-frags as PV A-frags. 4-deep cp.async KV ring.
// Epilogue writes fp16 O directly to g_oh [b,n,c].
// ---------------------------------------------------------------------------
#define ARS        144                    // row stride bytes
#define AQ_BYTES   (128*ARS)              // 18432
#define AKV_BYTES  (128*ARS)              // K(64)+V(64) per stage
#define ATTN_SMEM  (AQ_BYTES + 4*AKV_BYTES)   // 92160
#define NSTG32     32

__global__ __launch_bounds__(256, 2)
void attn_mma()
{
    extern __shared__ char smem[];
    const uint32_t sb = smem_u32(smem);
    const int tid  = threadIdx.x;
    const int lane = tid & 31, wid = tid >> 5;
    const int bh = blockIdx.y;
    const int n0 = blockIdx.x << 7;

    const __half* Qg = g_qh + (size_t)bh * SEQ * DH;
    const __half* Kg = g_kh + (size_t)bh * SEQ * DH;
    const __half* Vg = g_vh + (size_t)bh * SEQ * DH;

    const int qr  = (lane & 7) + ((lane >> 3) & 1)*8;   // A / V-trans grouping
    const int qc8 = ((lane >> 4) & 1)*8;
    const int kr  = (lane & 7) + ((lane >> 4) & 1)*8;   // K (B non-trans)
    const int kc8 = ((lane >> 3) & 1)*8;
    const int gid = lane >> 2, tg = lane & 3;
    const int i0 = wid*16;

    {
        const int crow = tid >> 3, cq = (tid & 7)*8;
#pragma unroll
        for (int i = 0; i < 4; ++i)
            cp16(sb + (crow + 32*i)*ARS + cq*2,
                 Qg + (size_t)(n0 + crow + 32*i)*DH + cq);
    }
    CP_COMMIT();

#define LOAD_KV(S, BUF) do {                                                  \
    const uint32_t kb = sb + AQ_BYTES + (BUF)*AKV_BYTES;                      \
    const int crow = tid >> 3, cq = (tid & 7)*8;                              \
    cp16(kb + crow*ARS + cq*2,        Kg + (size_t)((S)*64 + crow)*DH + cq);  \
    cp16(kb + (crow+32)*ARS + cq*2,   Kg + (size_t)((S)*64 + crow+32)*DH + cq);\
    cp16(kb + (crow+64)*ARS + cq*2,   Vg + (size_t)((S)*64 + crow)*DH + cq);  \
    cp16(kb + (crow+96)*ARS + cq*2,   Vg + (size_t)((S)*64 + crow+32)*DH + cq);\
} while (0)

    LOAD_KV(0, 0); CP_COMMIT();
    LOAD_KV(1, 1); CP_COMMIT();
    LOAD_KV(2, 2); CP_COMMIT();

    uint32_t qa[4][4];
    float oacc[8][4] = {};
    float m0r = -1e30f, m1r = -1e30f, l0r = 0.f, l1r = 0.f;

    for (int s = 0; s < NSTG32; ++s) {
        CP_WAIT_STAGE(s, NSTG32);
        __syncthreads();
        if (s == 0) {
#pragma unroll
            for (int t = 0; t < 4; ++t)
                ldsm4(qa[t], sb + (i0 + qr)*ARS + (16*t + qc8)*2);
        }
        if (s + 3 < NSTG32) LOAD_KV(s + 3, (s + 3) & 3);
        CP_COMMIT();

        const uint32_t kb = sb + AQ_BYTES + (s & 3)*AKV_BYTES;
        const uint32_t vb = kb + 64*ARS;

        // ---- S = Qs @ K^T (fp32 acc) ----
        float sacc[8][4] = {};
#pragma unroll
        for (int t = 0; t < 4; ++t) {
#pragma unroll
            for (int p = 0; p < 4; ++p) {
                uint32_t kf[4];
                ldsm4(kf, kb + (16*p + kr)*ARS + (16*t + kc8)*2);
                mma_h(sacc[2*p],   qa[t][0], qa[t][1], qa[t][2], qa[t][3],
                      kf[0], kf[1]);
                mma_h(sacc[2*p+1], qa[t][0], qa[t][1], qa[t][2], qa[t][3],
                      kf[2], kf[3]);
            }
        }

        // ---- online softmax (rows gid, gid+8) ----
        float mx0 = -1e30f, mx1 = -1e30f;
#pragma unroll
        for (int nt = 0; nt < 8; ++nt) {
            mx0 = fmaxf(mx0, fmaxf(sacc[nt][0], sacc[nt][1]));
            mx1 = fmaxf(mx1, fmaxf(sacc[nt][2], sacc[nt][3]));
        }
        mx0 = fmaxf(mx0, __shfl_xor_sync(0xffffffffu, mx0, 1));
        mx0 = fmaxf(mx0, __shfl_xor_sync(0xffffffffu, mx0, 2));
        mx1 = fmaxf(mx1, __shfl_xor_sync(0xffffffffu, mx1, 1));
        mx1 = fmaxf(mx1, __shfl_xor_sync(0xffffffffu, mx1, 2));
        const float mn0 = fmaxf(m0r, mx0), mn1 = fmaxf(m1r, mx1);
        const float co0 = __expf(m0r - mn0), co1 = __expf(m1r - mn1);
        m0r = mn0; m1r = mn1;

        uint32_t ph0[8], ph1[8];
        float ps0 = 0.f, ps1 = 0.f;
#pragma unroll
        for (int nt = 0; nt < 8; ++nt) {
            float p0 = __expf(sacc[nt][0] - mn0);
            float p1 = __expf(sacc[nt][1] - mn0);
            float p2 = __expf(sacc[nt][2] - mn1);
            float p3 = __expf(sacc[nt][3] - mn1);
            ps0 += p0 + p1; ps1 += p2 + p3;
            __half2 h01 = __floats2half2_rn(p0, p1);
            __half2 h23 = __floats2half2_rn(p2, p3);
            ph0[nt] = *reinterpret_cast<uint32_t*>(&h01);
            ph1[nt] = *reinterpret_cast<uint32_t*>(&h23);
            oacc[nt][0] *= co0; oacc[nt][1] *= co0;
            oacc[nt][2] *= co1; oacc[nt][3] *= co1;
        }
        ps0 += __shfl_xor_sync(0xffffffffu, ps0, 1);
        ps0 += __shfl_xor_sync(0xffffffffu, ps0, 2);
        ps1 += __shfl_xor_sync(0xffffffffu, ps1, 1);
        ps1 += __shfl_xor_sync(0xffffffffu, ps1, 2);
        l0r = l0r*co0 + ps0;
        l1r = l1r*co1 + ps1;

        // ---- O += P @ V ----
#pragma unroll
        for (int t = 0; t < 4; ++t) {
            const uint32_t a0 = ph0[2*t],   a1 = ph1[2*t];
            const uint32_t a2 = ph0[2*t+1], a3 = ph1[2*t+1];
#pragma unroll
            for (int q = 0; q < 4; ++q) {
                uint32_t vf[4];
                ldsm4t(vf, vb + (16*t + qr)*ARS + (16*q + qc8)*2);
                mma_h(oacc[2*q],   a0, a1, a2, a3, vf[0], vf[1]);
                mma_h(oacc[2*q+1], a0, a1, a2, a3, vf[2], vf[3]);
            }
        }
    }
#undef LOAD_KV

    // ---- epilogue: normalize, write fp16 O to g_oh [b,n,c] ----
    const int b = bh >> 4, h = bh & 15;
    const int n_r0 = n0 + i0 + gid;
    const size_t tok0 = (size_t)(b*SEQ + n_r0)*DIM;
    const size_t tok1 = (size_t)(b*SEQ + n_r0 + 8)*DIM;
    const float iv0 = 1.0f / l0r, iv1 = 1.0f / l1r;
#pragma unroll
    for (int nt = 0; nt < 8; ++nt) {
        const int c = h*64 + nt*8 + tg*2;
        *reinterpret_cast<__half2*>(&g_oh[tok0 + c]) =
            __floats2half2_rn(oacc[nt][0]*iv0, oacc[nt][1]*iv0);
        *reinterpret_cast<__half2*>(&g_oh[tok1 + c]) =
            __floats2half2_rn(oacc[nt][2]*iv1, oacc[nt][3]*iv1);
    }
}

// ---------------------------------------------------------------------------
extern "C" void kernel_launch(void* const* d_in, const int* in_sizes, int n_in,
                              void* d_out, int out_size)
{
    const float* x      = (const float*)d_in[0];
    const float* qkv_w  = (const float*)d_in[1];
    const float* qkv_b  = (const float*)d_in[2];
    const float* proj_w = (const float*)d_in[3];
    const float* proj_b = (const float*)d_in[4];
    float* out = (float*)d_out;

    cudaFuncSetAttribute(attn_mma, cudaFuncAttributeMaxDynamicSharedMemorySize,
                         ATTN_SMEM);
    cudaFuncSetAttribute(gemm_mma<0>,
                         cudaFuncAttributeMaxDynamicSharedMemorySize, GSMEM);
    cudaFuncSetAttribute(gemm_mma<1>,
                         cudaFuncAttributeMaxDynamicSharedMemorySize, GSMEM);

    __half *xh_p, *oh_p, *qw_p, *pw_p;
    cudaGetSymbolAddress((void**)&xh_p, g_xh);
    cudaGetSymbolAddress((void**)&oh_p, g_oh);
    cudaGetSymbolAddress((void**)&qw_p, g_qkvwh);
    cudaGetSymbolAddress((void**)&pw_p, g_projwh);

    dim3 blk(256);

    // 1) fp32 -> fp16 converts (x, weights)
    tofp16<<<(TOKENS*KDIM/4 + 255)/256, blk>>>(x,      xh_p, TOKENS*KDIM/4);
    tofp16<<<(QKV_N*KDIM/4  + 255)/256, blk>>>(qkv_w,  qw_p, QKV_N*KDIM/4);
    tofp16<<<(DIM*KDIM/4    + 255)/256, blk>>>(proj_w, pw_p, DIM*KDIM/4);

    // 2) QKV projection (fp16 mma, K=1024) -> fp16 q(0.125x)/k/v
    gemm_mma<0><<<dim3(QKV_N/128, TOKENS/128), blk, GSMEM>>>(
        xh_p, qw_p, qkv_b, nullptr);

    // 3) Tensor-core flash attention -> g_oh (fp16)
    attn_mma<<<dim3(SEQ/128, BATCH*NHEADS), blk, ATTN_SMEM>>>();

    // 4) Output projection (fp16 mma, K=1024) -> d_out (fp32)
    gemm_mma<1><<<dim3(DIM/128, TOKENS/128), blk, GSMEM>>>(
        oh_p, pw_p, proj_b, out);
}

// round 14
// speedup vs baseline: 10.3681x; 1.0505x over previous
#include <cuda_runtime.h>
#include <cuda_fp16.h>
#include <cstdint>

#define DIM    1024
#define BATCH  2
#define SEQ    2048
#define NHEADS 16
#define DH     64
#define TOKENS (BATCH*SEQ)      // 4096
#define QKV_N  (3*DIM)          // 3072
#define KDIM   1024

// ---------------- scratch (__device__ globals; allocation-free rule) --------
__device__ __align__(16) __half g_qh[BATCH*NHEADS*SEQ*DH]; // fp16 q (pre-scaled 0.125)
__device__ __align__(16) __half g_kh[BATCH*NHEADS*SEQ*DH]; // fp16 k
__device__ __align__(16) __half g_vh[BATCH*NHEADS*SEQ*DH]; // fp16 v

__device__ __align__(16) __half g_xh    [TOKENS*KDIM];     // x      fp16
__device__ __align__(16) __half g_oh    [TOKENS*DIM];      // attn O fp16 [b,n,c]
__device__ __align__(16) __half g_qkvwh [QKV_N*KDIM];      // qkv_w  fp16
__device__ __align__(16) __half g_projwh[DIM*KDIM];        // proj_w fp16

// ---------------------------------------------------------------------------
// PTX helpers (plain sm_80-era PTX; valid on compute_103)
// ---------------------------------------------------------------------------
__device__ __forceinline__ uint32_t smem_u32(const void* p) {
    uint32_t a;
    asm("{ .reg .u64 t; cvta.to.shared.u64 t, %1; cvt.u32.u64 %0, t; }"
        : "=r"(a) : "l"(p));
    return a;
}
__device__ __forceinline__ void cp16(uint32_t dst, const void* src) {
    asm volatile("cp.async.cg.shared.global [%0], [%1], 16;"
                 :: "r"(dst), "l"(src) : "memory");
}
#define CP_COMMIT() asm volatile("cp.async.commit_group;" ::: "memory")
#define CP_WAIT0()  asm volatile("cp.async.wait_group 0;"  ::: "memory")
#define CP_WAIT1()  asm volatile("cp.async.wait_group 1;"  ::: "memory")
#define CP_WAIT2()  asm volatile("cp.async.wait_group 2;"  ::: "memory")

__device__ __forceinline__ void ldsm4(uint32_t* r, uint32_t a) {
    asm volatile("ldmatrix.sync.aligned.m8n8.x4.shared.b16 {%0,%1,%2,%3}, [%4];"
                 : "=r"(r[0]), "=r"(r[1]), "=r"(r[2]), "=r"(r[3]) : "r"(a));
}
__device__ __forceinline__ void ldsm4t(uint32_t* r, uint32_t a) {
    asm volatile("ldmatrix.sync.aligned.m8n8.x4.trans.shared.b16 {%0,%1,%2,%3}, [%4];"
                 : "=r"(r[0]), "=r"(r[1]), "=r"(r[2]), "=r"(r[3]) : "r"(a));
}
__device__ __forceinline__ void mma_h(float* c, uint32_t a0, uint32_t a1,
                                      uint32_t a2, uint32_t a3,
                                      uint32_t b0, uint32_t b1) {
    asm volatile(
        "mma.sync.aligned.m16n8k16.row.col.f32.f16.f16.f32 "
        "{%0,%1,%2,%3}, {%4,%5,%6,%7}, {%8,%9}, {%0,%1,%2,%3};"
        : "+f"(c[0]), "+f"(c[1]), "+f"(c[2]), "+f"(c[3])
        : "r"(a0), "r"(a1), "r"(a2), "r"(a3), "r"(b0), "r"(b1));
}

// ---------------------------------------------------------------------------
// tofp16_all: one launch converting x, qkv_w, proj_w fp32->fp16 (float4 granule)
// ---------------------------------------------------------------------------
#define N0_4 (TOKENS*KDIM/4)                 // 1048576
#define N1_4 (QKV_N*KDIM/4)                  //  786432
#define N2_4 (DIM*KDIM/4)                    //  262144
#define NALL4 (N0_4 + N1_4 + N2_4)           // 2097152

__global__ __launch_bounds__(256)
void tofp16_all(const float* __restrict__ x, const float* __restrict__ qw,
                const float* __restrict__ pw)
{
    int i = blockIdx.x*256 + threadIdx.x;
    const float* s; __half* d;
    if (i < N0_4)              { s = x;  d = g_xh;     }
    else if (i < N0_4 + N1_4)  { s = qw; d = g_qkvwh;  i -= N0_4; }
    else                       { s = pw; d = g_projwh; i -= N0_4 + N1_4; }
    float4 v = reinterpret_cast<const float4*>(s)[i];
    __half2 h01 = __floats2half2_rn(v.x, v.y);
    __half2 h23 = __floats2half2_rn(v.z, v.w);
    uint2 pk;
    pk.x = *reinterpret_cast<uint32_t*>(&h01);
    pk.y = *reinterpret_cast<uint32_t*>(&h23);
    reinterpret_cast<uint2*>(d)[i] = pk;
}

// ---------------------------------------------------------------------------
// mma.sync fp16 GEMM: C = A[M,1024] @ W[Nout,1024]^T + bias (fp32 acc).
// BM=BN=128, BK=64 (attention-matched stage density: 64 MMAs/warp/stage),
// 8 warps (2m x 4n), 3-buffer cp.async ring, 2 stages in flight, uniform
// wait_group 1 (exact under always-commit). ldsm interleaved with MMA.
// MODE 0: write q/k/v as fp16 (q pre-scaled 0.125). MODE 1: fp32 out.
// ---------------------------------------------------------------------------
#define BK         64
#define GARS       144                     // row stride bytes (128B data + 16)
#define STAGE_OPER (128*GARS)              // 18432
#define STAGE_B    (2*STAGE_OPER)          // 36864
#define GSMEM      (3*STAGE_B)             // 110592
#define NSTG       (KDIM/BK)               // 16

__device__ __forceinline__ void store_qkv_h(int m, int col, float x, float y) {
    const int c3 = col >> 10;
    const int h  = (col >> 6) & 15, d = col & 63;
    const int b  = m >> 11,  n = m & 2047;
    const float sc = (c3 == 0) ? 0.125f : 1.0f;
    __half* p = (c3 == 0) ? g_qh : (c3 == 1) ? g_kh : g_vh;
    *reinterpret_cast<__half2*>(
        &p[((size_t)((b << 4) + h)*SEQ + n)*DH + d]) =
        __floats2half2_rn(x*sc, y*sc);
}

template<int MODE>
__global__ __launch_bounds__(256, 2)
void gemm_mma(const __half* __restrict__ Ag, const __half* __restrict__ Wg,
              const float* __restrict__ bias, float* __restrict__ outp)
{
    extern __shared__ char smem[];
    const uint32_t sbase = smem_u32(smem);
    const int tid  = threadIdx.x;
    const int lane = tid & 31, wid = tid >> 5;
    const int warp_m = wid >> 2, warp_n = wid & 3;
    const int m0 = blockIdx.y << 7, n0 = blockIdx.x << 7;

    // 8 cp16/thread/stage: chunks c = tid + 256*i, row=c>>3 (0..127), q=c&7
    const int crow = tid >> 3, cq = tid & 7;

    const __half* Ab = Ag + (size_t)m0*KDIM;
    const __half* Wb = Wg + (size_t)n0*KDIM;

#define LOAD_STAGE(S, BUF) do {                                               \
    const uint32_t sa = sbase + (BUF)*STAGE_B;                                \
    const uint32_t sw = sa + STAGE_OPER;                                      \
    const size_t ko = (size_t)(S)*BK + cq*8;                                  \
    _Pragma("unroll")                                                         \
    for (int i_ = 0; i_ < 4; ++i_) {                                          \
        const int r_ = crow + 32*i_;                                          \
        cp16(sa + r_*GARS + cq*16, Ab + (size_t)r_*KDIM + ko);                \
        cp16(sw + r_*GARS + cq*16, Wb + (size_t)r_*KDIM + ko);                \
    }                                                                         \
} while (0)

    const uint32_t a_off = (uint32_t)((warp_m*64 + (lane & 15))*GARS
                                      + (lane >> 4)*16);
    const uint32_t b_off = (uint32_t)((warp_n*32 + (lane & 7)
                                      + ((lane >> 4) & 1)*8)*GARS
                                      + ((lane >> 3) & 1)*16);

    float acc[4][4][4] = {};

    LOAD_STAGE(0, 0); CP_COMMIT();
    LOAD_STAGE(1, 1); CP_COMMIT();

    for (int s = 0; s < NSTG; ++s) {
        CP_WAIT1();                      // stage s resident (exact: only s+1 may pend)
        __syncthreads();                 // buffer (s+2)%3 fully consumed (iter s-1)
        if (s + 2 < NSTG) LOAD_STAGE(s + 2, (s + 2) % 3);
        CP_COMMIT();                     // always commit (uniform group count)

        const uint32_t ab = sbase + (s % 3)*STAGE_B;
        const uint32_t bb = ab + STAGE_OPER;
#pragma unroll
        for (int kk = 0; kk < 4; ++kk) {
            uint32_t bf[2][4];
            ldsm4(bf[0], bb + b_off + kk*32);
            ldsm4(bf[1], bb + b_off + 16*GARS + kk*32);
#pragma unroll
            for (int mt = 0; mt < 4; ++mt) {
                uint32_t af[4];
                ldsm4(af, ab + a_off + mt*16*GARS + kk*32);
#pragma unroll
                for (int nt = 0; nt < 4; ++nt)
                    mma_h(acc[mt][nt], af[0], af[1], af[2], af[3],
                          bf[nt >> 1][(nt & 1)*2],
                          bf[nt >> 1][(nt & 1)*2 + 1]);
            }
        }
    }
#undef LOAD_STAGE

    const int gr = lane >> 2, tg = lane & 3;
#pragma unroll
    for (int mt = 0; mt < 4; ++mt) {
        const int r0 = m0 + warp_m*64 + mt*16 + gr;
#pragma unroll
        for (int nt = 0; nt < 4; ++nt) {
            const int col = n0 + warp_n*32 + nt*8 + tg*2;
            const float2 bv = *reinterpret_cast<const float2*>(bias + col);
            const float v00 = acc[mt][nt][0] + bv.x;
            const float v01 = acc[mt][nt][1] + bv.y;
            const float v10 = acc[mt][nt][2] + bv.x;
            const float v11 = acc[mt][nt][3] + bv.y;
            if (MODE == 0) {
                store_qkv_h(r0,     col, v00, v01);
                store_qkv_h(r0 + 8, col, v10, v11);
            } else {
                *reinterpret_cast<float2*>(&outp[(size_t)r0*DIM + col]) =
                    make_float2(v00, v01);
                *reinterpret_cast<float2*>(&outp[(size_t)(r0+8)*DIM + col]) =
                    make_float2(v10, v11);
            }
        }
    }
}

// ---------------------------------------------------------------------------
// Tensor-core flash attention (fp16 mma.sync, fp32 softmax/accum) — R12 proven.
// ---------------------------------------------------------------------------
#define ARS        144
#define AQ_BYTES   (128*ARS)
#define AKV_BYTES  (128*ARS)
#define ATTN_SMEM  (AQ_BYTES + 4*AKV_BYTES)   // 92160
#define NSTG32     32
#define CP_WAIT_STAGE(S, NS) do {                  \
    if      ((S) + 2 < (NS)) CP_WAIT2();           \
    else if ((S) + 1 < (NS)) CP_WAIT1();           \
    else                     CP_WAIT0();           \
} while (0)

__global__ __launch_bounds__(256, 2)
void attn_mma()
{
    extern __shared__ char smem[];
    const uint32_t sb = smem_u32(smem);
    const int tid  = threadIdx.x;
    const int lane = tid & 31, wid = tid >> 5;
    const int bh = blockIdx.y;
    const int n0 = blockIdx.x << 7;

    const __half* Qg = g_qh + (size_t)bh * SEQ * DH;
    const __half* Kg = g_kh + (size_t)bh * SEQ * DH;
    const __half* Vg = g_vh + (size_t)bh * SEQ * DH;

    const int qr  = (lane & 7) + ((lane >> 3) & 1)*8;
    const int qc8 = ((lane >> 4) & 1)*8;
    const int kr  = (lane & 7) + ((lane >> 4) & 1)*8;
    const int kc8 = ((lane >> 3) & 1)*8;
    const int gid = lane >> 2, tg = lane & 3;
    const int i0 = wid*16;

    {
        const int crow = tid >> 3, cq = (tid & 7)*8;
#pragma unroll
        for (int i = 0; i < 4; ++i)
            cp16(sb + (crow + 32*i)*ARS + cq*2,
                 Qg + (size_t)(n0 + crow + 32*i)*DH + cq);
    }
    CP_COMMIT();

#define LOAD_KV(S, BUF) do {                                                  \
    const uint32_t kb = sb + AQ_BYTES + (BUF)*AKV_BYTES;                      \
    const int crow = tid >> 3, cq = (tid & 7)*8;                              \
    cp16(kb + crow*ARS + cq*2,        Kg + (size_t)((S)*64 + crow)*DH + cq);  \
    cp16(kb + (crow+32)*ARS + cq*2,   Kg + (size_t)((S)*64 + crow+32)*DH + cq);\
    cp16(kb + (crow+64)*ARS + cq*2,   Vg + (size_t)((S)*64 + crow)*DH + cq);  \
    cp16(kb + (crow+96)*ARS + cq*2,   Vg + (size_t)((S)*64 + crow+32)*DH + cq);\
} while (0)

    LOAD_KV(0, 0); CP_COMMIT();
    LOAD_KV(1, 1); CP_COMMIT();
    LOAD_KV(2, 2); CP_COMMIT();

    uint32_t qa[4][4];
    float oacc[8][4] = {};
    float m0r = -1e30f, m1r = -1e30f, l0r = 0.f, l1r = 0.f;

    for (int s = 0; s < NSTG32; ++s) {
        CP_WAIT_STAGE(s, NSTG32);
        __syncthreads();
        if (s == 0) {
#pragma unroll
            for (int t = 0; t < 4; ++t)
                ldsm4(qa[t], sb + (i0 + qr)*ARS + (16*t + qc8)*2);
        }
        if (s + 3 < NSTG32) LOAD_KV(s + 3, (s + 3) & 3);
        CP_COMMIT();

        const uint32_t kb = sb + AQ_BYTES + (s & 3)*AKV_BYTES;
        const uint32_t vb = kb + 64*ARS;

        float sacc[8][4] = {};
#pragma unroll
        for (int t = 0; t < 4; ++t) {
#pragma unroll
            for (int p = 0; p < 4; ++p) {
                uint32_t kf[4];
                ldsm4(kf, kb + (16*p + kr)*ARS + (16*t + kc8)*2);
                mma_h(sacc[2*p],   qa[t][0], qa[t][1], qa[t][2], qa[t][3],
                      kf[0], kf[1]);
                mma_h(sacc[2*p+1], qa[t][0], qa[t][1], qa[t][2], qa[t][3],
                      kf[2], kf[3]);
            }
        }

        float mx0 = -1e30f, mx1 = -1e30f;
#pragma unroll
        for (int nt = 0; nt < 8; ++nt) {
            mx0 = fmaxf(mx0, fmaxf(sacc[nt][0], sacc[nt][1]));
            mx1 = fmaxf(mx1, fmaxf(sacc[nt][2], sacc[nt][3]));
        }
        mx0 = fmaxf(mx0, __shfl_xor_sync(0xffffffffu, mx0, 1));
        mx0 = fmaxf(mx0, __shfl_xor_sync(0xffffffffu, mx0, 2));
        mx1 = fmaxf(mx1, __shfl_xor_sync(0xffffffffu, mx1, 1));
        mx1 = fmaxf(mx1, __shfl_xor_sync(0xffffffffu, mx1, 2));
        const float mn0 = fmaxf(m0r, mx0), mn1 = fmaxf(m1r, mx1);
        const float co0 = __expf(m0r - mn0), co1 = __expf(m1r - mn1);
        m0r = mn0; m1r = mn1;

        uint32_t ph0[8], ph1[8];
        float ps0 = 0.f, ps1 = 0.f;
#pragma unroll
        for (int nt = 0; nt < 8; ++nt) {
            float p0 = __expf(sacc[nt][0] - mn0);
            float p1 = __expf(sacc[nt][1] - mn0);
            float p2 = __expf(sacc[nt][2] - mn1);
            float p3 = __expf(sacc[nt][3] - mn1);
            ps0 += p0 + p1; ps1 += p2 + p3;
            __half2 h01 = __floats2half2_rn(p0, p1);
            __half2 h23 = __floats2half2_rn(p2, p3);
            ph0[nt] = *reinterpret_cast<uint32_t*>(&h01);
            ph1[nt] = *reinterpret_cast<uint32_t*>(&h23);
            oacc[nt][0] *= co0; oacc[nt][1] *= co0;
            oacc[nt][2] *= co1; oacc[nt][3] *= co1;
        }
        ps0 += __shfl_xor_sync(0xffffffffu, ps0, 1);
        ps0 += __shfl_xor_sync(0xffffffffu, ps0, 2);
        ps1 += __shfl_xor_sync(0xffffffffu, ps1, 1);
        ps1 += __shfl_xor_sync(0xffffffffu, ps1, 2);
        l0r = l0r*co0 + ps0;
        l1r = l1r*co1 + ps1;

#pragma unroll
        for (int t = 0; t < 4; ++t) {
            const uint32_t a0 = ph0[2*t],   a1 = ph1[2*t];
            const uint32_t a2 = ph0[2*t+1], a3 = ph1[2*t+1];
#pragma unroll
            for (int q = 0; q < 4; ++q) {
                uint32_t vf[4];
                ldsm4t(vf, vb + (16*t + qr)*ARS + (16*q + qc8)*2);
                mma_h(oacc[2*q],   a0, a1, a2, a3, vf[0], vf[1]);
                mma_h(oacc[2*q+1], a0, a1, a2, a3, vf[2], vf[3]);
            }
        }
    }
#undef LOAD_KV

    const int b = bh >> 4, h = bh & 15;
    const int n_r0 = n0 + i0 + gid;
    const size_t tok0 = (size_t)(b*SEQ + n_r0)*DIM;
    const size_t tok1 = (size_t)(b*SEQ + n_r0 + 8)*DIM;
    const float iv0 = 1.0f / l0r, iv1 = 1.0f / l1r;
#pragma unroll
    for (int nt = 0; nt < 8; ++nt) {
        const int c = h*64 + nt*8 + tg*2;
        *reinterpret_cast<__half2*>(&g_oh[tok0 + c]) =
            __floats2half2_rn(oacc[nt][0]*iv0, oacc[nt][1]*iv0);
        *reinterpret_cast<__half2*>(&g_oh[tok1 + c]) =
            __floats2half2_rn(oacc[nt][2]*iv1, oacc[nt][3]*iv1);
    }
}

// ---------------------------------------------------------------------------
extern "C" void kernel_launch(void* const* d_in, const int* in_sizes, int n_in,
                              void* d_out, int out_size)
{
    const float* x      = (const float*)d_in[0];
    const float* qkv_w  = (const float*)d_in[1];
    const float* qkv_b  = (const float*)d_in[2];
    const float* proj_w = (const float*)d_in[3];
    const float* proj_b = (const float*)d_in[4];
    float* out = (float*)d_out;

    cudaFuncSetAttribute(attn_mma, cudaFuncAttributeMaxDynamicSharedMemorySize,
                         ATTN_SMEM);
    cudaFuncSetAttribute(gemm_mma<0>,
                         cudaFuncAttributeMaxDynamicSharedMemorySize, GSMEM);
    cudaFuncSetAttribute(gemm_mma<1>,
                         cudaFuncAttributeMaxDynamicSharedMemorySize, GSMEM);

    __half *xh_p, *oh_p, *qw_p, *pw_p;
    cudaGetSymbolAddress((void**)&xh_p, g_xh);
    cudaGetSymbolAddress((void**)&oh_p, g_oh);
    cudaGetSymbolAddress((void**)&qw_p, g_qkvwh);
    cudaGetSymbolAddress((void**)&pw_p, g_projwh);

    dim3 blk(256);

    // 1) fp32 -> fp16 converts (single fused launch)
    tofp16_all<<<NALL4/256, blk>>>(x, qkv_w, proj_w);

    // 2) QKV projection (fp16 mma, BK=64) -> fp16 q(0.125x)/k/v
    gemm_mma<0><<<dim3(QKV_N/128, TOKENS/128), blk, GSMEM>>>(
        xh_p, qw_p, qkv_b, nullptr);

    // 3) Tensor-core flash attention -> g_oh (fp16)
    attn_mma<<<dim3(SEQ/128, BATCH*NHEADS), blk, ATTN_SMEM>>>();

    // 4) Output projection (fp16 mma, BK=64) -> d_out (fp32)
    gemm_mma<1><<<dim3(DIM/128, TOKENS/128), blk, GSMEM>>>(
        oh_p, pw_p, proj_b, out);
}